// round 7
// baseline (speedup 1.0000x reference)
#include <cuda_runtime.h>
#include <math.h>
#include <math_constants.h>
#include <stdint.h>

// Problem constants
#define BB 2
#define NN 2048
#define DIMX 768
#define HH 8
#define FF 192
#define LREL 4095            // 2*N - 1
#define QKVW 512             // H * DK

// ---------------- scratch (device globals; no allocation allowed) ----------
__device__ __align__(256) float g_pos[(size_t)LREL * FF];      // 3.1 MB
__device__ __align__(256) float g_relk[(size_t)LREL * QKVW];   // 8.4 MB  [idx][h*64+d]
__device__ __align__(256) float g_q[(size_t)BB * NN * QKVW];   // 8.4 MB  [b][n][h*64+d]
__device__ __align__(256) float g_k[(size_t)BB * NN * QKVW];
__device__ __align__(256) float g_v[(size_t)BB * NN * QKVW];
__device__ __align__(256) float g_o[(size_t)BB * NN * QKVW];
__device__ __align__(256) float g_S[(size_t)BB * HH * NN * NN]; // 268 MB

// ---------------- tf32 mma helpers -----------------------------------------
__device__ __forceinline__ uint32_t f2tf(float x) {
    uint32_t r;
    asm("cvt.rna.tf32.f32 %0, %1;" : "=r"(r) : "f"(x));
    return r;
}
// two-term split: x ~= hi + lo, both representable in tf32
__device__ __forceinline__ void tfsplit(float x, uint32_t& hi, uint32_t& lo) {
    hi = f2tf(x);
    lo = f2tf(x - __uint_as_float(hi));
}

// D += A(m16k8,row) * B(k8n8,col)   fragments per PTX ISA m16n8k8 tf32
__device__ __forceinline__ void mma8(float* d, const uint32_t* a, const uint32_t* b) {
    asm volatile(
        "mma.sync.aligned.m16n8k8.row.col.f32.tf32.tf32.f32 "
        "{%0,%1,%2,%3},{%4,%5,%6,%7},{%8,%9},{%0,%1,%2,%3};\n"
        : "+f"(d[0]), "+f"(d[1]), "+f"(d[2]), "+f"(d[3])
        : "r"(a[0]), "r"(a[1]), "r"(a[2]), "r"(a[3]), "r"(b[0]), "r"(b[1]));
}
// tf32x3 accumulate: d += ahi*bhi + ahi*blo + alo*bhi
__device__ __forceinline__ void mma8x3(float* d, const uint32_t* ahi, const uint32_t* alo,
                                       const uint32_t* bhi, const uint32_t* blo) {
    mma8(d, ahi, blo);
    mma8(d, alo, bhi);
    mma8(d, ahi, bhi);
}

// ---------------- K1: positional embedding ----------------------------------
__global__ void pos_embed_kernel() {
    int row = blockIdx.x;            // 0..4094
    int i = threadIdx.x;             // 0..31
    float dist = (float)(row - (NN - 1));
    float ad = fabsf(dist);

    float half_life = exp2f(3.0f + 8.0f * (float)i / 31.0f);
    float f_exp = exp2f(-ad / half_life);

    float width = exp2f((float)(i + 1)) - 1.0f;
    float f_cm = (width > ad) ? 1.0f : 0.0f;

    float mean = 64.0f * (float)(i + 1);
    float conc = (mean / 32.0f) * (mean / 32.0f);
    float rate = mean / 1024.0f;
    float log_unnorm = (conc - 1.0f) * logf(ad) - rate * ad;
    float log_norm = lgammaf(conc) - conc * logf(rate);
    float prob = expf(log_unnorm - log_norm) + 1e-8f;
    float pmax = prob;
    #pragma unroll
    for (int o = 16; o; o >>= 1) pmax = fmaxf(pmax, __shfl_xor_sync(0xFFFFFFFFu, pmax, o));
    float f_g = prob / pmax;

    float sgn = (dist > 0.0f) ? 1.0f : ((dist < 0.0f) ? -1.0f : 0.0f);

    float* out = g_pos + (size_t)row * FF;
    out[i]       = f_exp;
    out[32 + i]  = f_cm;
    out[64 + i]  = f_g;
    out[96 + i]  = sgn * f_exp;
    out[128 + i] = sgn * f_cm;
    out[160 + i] = sgn * f_g;
}

// ---------------- K2: generic tf32x3 tensor-core GEMM -----------------------
// C[M,Nc] = A[M,K] @ B[K,Nc] (+bias), strided; pvmode batches over blockIdx.z (bh).
// Block tile 128x64, 8 warps (4m x 2n), warp tile 32x32, k-step 32.
#define AS_STRIDE 136   // m-stride of As[k][m]
#define BS_STRIDE 72    // n-stride of Bs[k][n]
__global__ void gemm_tf32(const float* __restrict__ A, const float* __restrict__ B,
                          const float* __restrict__ bias, float* __restrict__ C,
                          int M, int K, int Nc, int lda, int ldb, int ldc, int pvmode) {
    __shared__ float As[32 * AS_STRIDE];
    __shared__ float Bs[32 * BS_STRIDE];

    if (pvmode) {
        int z = blockIdx.z;
        A += (size_t)z * NN * NN;
        size_t off = (size_t)(z >> 3) * NN * QKVW + (size_t)(z & 7) * 64;
        B += off;
        C += off;
    }

    int tid = threadIdx.x;
    int warp = tid >> 5, lane = tid & 31;
    int g = lane >> 2, tig = lane & 3;
    int mw = (warp >> 1) * 32, nw = (warp & 1) * 32;
    int m0 = blockIdx.y * 128, n0 = blockIdx.x * 64;

    float acc[2][4][4] = {};

    int arow = tid >> 3;            // 0..31
    int ak = (tid & 7) * 4;         // 0..28
    int bk = tid >> 3;              // 0..31
    int bn = (tid & 7) * 8;         // 0..56

    for (int k0 = 0; k0 < K; k0 += 32) {
        #pragma unroll
        for (int r = 0; r < 4; r++) {
            int ml = arow + 32 * r;
            int m = m0 + ml;
            float4 av = make_float4(0.f, 0.f, 0.f, 0.f);
            if (m < M) av = *(const float4*)(A + (size_t)m * lda + k0 + ak);
            As[(ak + 0) * AS_STRIDE + ml] = av.x;
            As[(ak + 1) * AS_STRIDE + ml] = av.y;
            As[(ak + 2) * AS_STRIDE + ml] = av.z;
            As[(ak + 3) * AS_STRIDE + ml] = av.w;
        }
        {
            const float* bp = B + (size_t)(k0 + bk) * ldb + n0 + bn;
            float4 b0 = *(const float4*)bp;
            float4 b1 = *(const float4*)(bp + 4);
            Bs[bk * BS_STRIDE + bn + 0] = b0.x;
            Bs[bk * BS_STRIDE + bn + 1] = b0.y;
            Bs[bk * BS_STRIDE + bn + 2] = b0.z;
            Bs[bk * BS_STRIDE + bn + 3] = b0.w;
            Bs[bk * BS_STRIDE + bn + 4] = b1.x;
            Bs[bk * BS_STRIDE + bn + 5] = b1.y;
            Bs[bk * BS_STRIDE + bn + 6] = b1.z;
            Bs[bk * BS_STRIDE + bn + 7] = b1.w;
        }
        __syncthreads();
        #pragma unroll
        for (int kk = 0; kk < 32; kk += 8) {
            uint32_t ah[2][4], al[2][4];
            #pragma unroll
            for (int f = 0; f < 2; f++) {
                int mb = mw + 16 * f;
                tfsplit(As[(kk + tig) * AS_STRIDE + mb + g],         ah[f][0], al[f][0]);
                tfsplit(As[(kk + tig) * AS_STRIDE + mb + g + 8],     ah[f][1], al[f][1]);
                tfsplit(As[(kk + tig + 4) * AS_STRIDE + mb + g],     ah[f][2], al[f][2]);
                tfsplit(As[(kk + tig + 4) * AS_STRIDE + mb + g + 8], ah[f][3], al[f][3]);
            }
            #pragma unroll
            for (int j = 0; j < 4; j++) {
                uint32_t bh2[2], bl2[2];
                tfsplit(Bs[(kk + tig) * BS_STRIDE + nw + 8 * j + g],     bh2[0], bl2[0]);
                tfsplit(Bs[(kk + tig + 4) * BS_STRIDE + nw + 8 * j + g], bh2[1], bl2[1]);
                mma8x3(acc[0][j], ah[0], al[0], bh2, bl2);
                mma8x3(acc[1][j], ah[1], al[1], bh2, bl2);
            }
        }
        __syncthreads();
    }

    #pragma unroll
    for (int f = 0; f < 2; f++) {
        #pragma unroll
        for (int j = 0; j < 4; j++) {
            int n = n0 + nw + 8 * j + 2 * tig;
            float b0v = bias ? bias[n] : 0.0f;
            float b1v = bias ? bias[n + 1] : 0.0f;
            int m = m0 + mw + 16 * f + g;
            if (m < M)
                *(float2*)(C + (size_t)m * ldc + n) =
                    make_float2(acc[f][j][0] + b0v, acc[f][j][1] + b1v);
            if (m + 8 < M)
                *(float2*)(C + (size_t)(m + 8) * ldc + n) =
                    make_float2(acc[f][j][2] + b0v, acc[f][j][3] + b1v);
        }
    }
}

// ---------------- K3: logits via tf32x3 mma + Toeplitz band gather ----------
// S[b,h,i,j] = (0.125*q_i + rcb_h).k_j + (0.125*q_i + rpb_h).relk[j-i+N-1]
#define QS_STRIDE 72
#define RS_STRIDE 136
__global__ void logits_tf32(const float* __restrict__ rcb, const float* __restrict__ rpb) {
    extern __shared__ float sm[];
    float* Qs = sm;                         // [64][QS_STRIDE]: Qs[d*72 + li]
    float* Rs = sm + 64 * QS_STRIDE;        // [64][RS_STRIDE]: Rs[d*136 + u]
    float* Gs = Rs;                         // reuse: Gs[li*136 + u]

    int bh = blockIdx.z;
    int b = bh >> 3, h = bh & 7;
    int i0 = blockIdx.y * 64, j0 = blockIdx.x * 64;
    int tid = threadIdx.x;
    int warp = tid >> 5, lane = tid & 31;
    int g = lane >> 2, tig = lane & 3;
    int mwl = (warp >> 1) * 16;       // warp row base (4 warps over 64 rows)
    int nwl = (warp & 1) * 32;        // content col base (2 warps over 64 cols)

    const float* qb = g_q + (size_t)b * NN * QKVW + (size_t)h * 64;
    const float* kb = g_k + (size_t)b * NN * QKVW + (size_t)h * 64;

    int d4 = (tid & 15) * 4;
    int lrow = tid >> 4;              // 0..15
    float4 rc = *(const float4*)(rcb + h * 64 + d4);
    float4 rp = *(const float4*)(rpb + h * 64 + d4);

    // ---- phase A loads ----
    #pragma unroll
    for (int r = 0; r < 4; r++) {
        int li = lrow + 16 * r;
        float4 qv = *(const float4*)(qb + (size_t)(i0 + li) * QKVW + d4);
        Qs[(d4 + 0) * QS_STRIDE + li] = qv.x * 0.125f + rc.x;
        Qs[(d4 + 1) * QS_STRIDE + li] = qv.y * 0.125f + rc.y;
        Qs[(d4 + 2) * QS_STRIDE + li] = qv.z * 0.125f + rc.z;
        Qs[(d4 + 3) * QS_STRIDE + li] = qv.w * 0.125f + rc.w;
        float4 kv = *(const float4*)(kb + (size_t)(j0 + li) * QKVW + d4);
        Rs[(d4 + 0) * RS_STRIDE + li] = kv.x;
        Rs[(d4 + 1) * RS_STRIDE + li] = kv.y;
        Rs[(d4 + 2) * RS_STRIDE + li] = kv.z;
        Rs[(d4 + 3) * RS_STRIDE + li] = kv.w;
    }
    __syncthreads();

    float cacc[4][4] = {};
    #pragma unroll
    for (int kk = 0; kk < 64; kk += 8) {
        uint32_t ah[4], al[4];
        tfsplit(Qs[(kk + tig) * QS_STRIDE + mwl + g],         ah[0], al[0]);
        tfsplit(Qs[(kk + tig) * QS_STRIDE + mwl + g + 8],     ah[1], al[1]);
        tfsplit(Qs[(kk + tig + 4) * QS_STRIDE + mwl + g],     ah[2], al[2]);
        tfsplit(Qs[(kk + tig + 4) * QS_STRIDE + mwl + g + 8], ah[3], al[3]);
        #pragma unroll
        for (int j = 0; j < 4; j++) {
            uint32_t bh2[2], bl2[2];
            tfsplit(Rs[(kk + tig) * RS_STRIDE + nwl + 8 * j + g],     bh2[0], bl2[0]);
            tfsplit(Rs[(kk + tig + 4) * RS_STRIDE + nwl + 8 * j + g], bh2[1], bl2[1]);
            mma8x3(cacc[j], ah, al, bh2, bl2);
        }
    }
    __syncthreads();

    // ---- phase B: G[64x128] = Qp @ relband^T ----
    int base = j0 - i0 + (NN - 1) - 63;   // band [base, base+128)
    #pragma unroll
    for (int r = 0; r < 4; r++) {
        int li = lrow + 16 * r;
        float4 qv = *(const float4*)(qb + (size_t)(i0 + li) * QKVW + d4);
        Qs[(d4 + 0) * QS_STRIDE + li] = qv.x * 0.125f + rp.x;
        Qs[(d4 + 1) * QS_STRIDE + li] = qv.y * 0.125f + rp.y;
        Qs[(d4 + 2) * QS_STRIDE + li] = qv.z * 0.125f + rp.z;
        Qs[(d4 + 3) * QS_STRIDE + li] = qv.w * 0.125f + rp.w;
    }
    #pragma unroll
    for (int r = 0; r < 8; r++) {
        int u = lrow + 16 * r;
        float4 rv = *(const float4*)(g_relk + (size_t)(base + u) * QKVW + h * 64 + d4);
        Rs[(d4 + 0) * RS_STRIDE + u] = rv.x;
        Rs[(d4 + 1) * RS_STRIDE + u] = rv.y;
        Rs[(d4 + 2) * RS_STRIDE + u] = rv.z;
        Rs[(d4 + 3) * RS_STRIDE + u] = rv.w;
    }
    __syncthreads();

    float gacc[8][4] = {};
    int nwg = (warp & 1) * 64;
    #pragma unroll
    for (int kk = 0; kk < 64; kk += 8) {
        uint32_t ah[4], al[4];
        tfsplit(Qs[(kk + tig) * QS_STRIDE + mwl + g],         ah[0], al[0]);
        tfsplit(Qs[(kk + tig) * QS_STRIDE + mwl + g + 8],     ah[1], al[1]);
        tfsplit(Qs[(kk + tig + 4) * QS_STRIDE + mwl + g],     ah[2], al[2]);
        tfsplit(Qs[(kk + tig + 4) * QS_STRIDE + mwl + g + 8], ah[3], al[3]);
        #pragma unroll
        for (int j = 0; j < 8; j++) {
            uint32_t bh2[2], bl2[2];
            tfsplit(Rs[(kk + tig) * RS_STRIDE + nwg + 8 * j + g],     bh2[0], bl2[0]);
            tfsplit(Rs[(kk + tig + 4) * RS_STRIDE + nwg + 8 * j + g], bh2[1], bl2[1]);
            mma8x3(gacc[j], ah, al, bh2, bl2);
        }
    }
    __syncthreads();   // all warps done reading Rs

    #pragma unroll
    for (int j = 0; j < 8; j++) {
        int u = nwg + 8 * j + 2 * tig;
        int li = mwl + g;
        *(float2*)&Gs[li * RS_STRIDE + u] = make_float2(gacc[j][0], gacc[j][1]);
        *(float2*)&Gs[(li + 8) * RS_STRIDE + u] = make_float2(gacc[j][2], gacc[j][3]);
    }
    __syncthreads();

    float* Sout = g_S + ((size_t)bh * NN + i0) * NN + j0;
    #pragma unroll
    for (int j = 0; j < 4; j++) {
        int lj = nwl + 8 * j + 2 * tig;
        int li = mwl + g;
        float o0 = cacc[j][0] + Gs[li * RS_STRIDE + (lj - li + 63)];
        float o1 = cacc[j][1] + Gs[li * RS_STRIDE + (lj + 1 - li + 63)];
        *(float2*)(Sout + (size_t)li * NN + lj) = make_float2(o0, o1);
        int li2 = li + 8;
        float o2 = cacc[j][2] + Gs[li2 * RS_STRIDE + (lj - li2 + 63)];
        float o3 = cacc[j][3] + Gs[li2 * RS_STRIDE + (lj + 1 - li2 + 63)];
        *(float2*)(Sout + (size_t)li2 * NN + lj) = make_float2(o2, o3);
    }
}

// ---------------- K4: row softmax over 2048 (vectorized) --------------------
__global__ void softmax_kernel() {
    size_t row = blockIdx.x;
    float4* Sr = (float4*)(g_S + row * NN);
    int tid = threadIdx.x;
    __shared__ float red[8];
    __shared__ float bcast;

    float4 v0 = Sr[tid];
    float4 v1 = Sr[tid + 256];
    float m = fmaxf(fmaxf(fmaxf(v0.x, v0.y), fmaxf(v0.z, v0.w)),
                    fmaxf(fmaxf(v1.x, v1.y), fmaxf(v1.z, v1.w)));
    #pragma unroll
    for (int o = 16; o; o >>= 1) m = fmaxf(m, __shfl_xor_sync(0xFFFFFFFFu, m, o));
    if ((tid & 31) == 0) red[tid >> 5] = m;
    __syncthreads();
    if (tid == 0) {
        float mm = red[0];
        #pragma unroll
        for (int w = 1; w < 8; w++) mm = fmaxf(mm, red[w]);
        bcast = mm;
    }
    __syncthreads();
    m = bcast;

    v0.x = expf(v0.x - m); v0.y = expf(v0.y - m); v0.z = expf(v0.z - m); v0.w = expf(v0.w - m);
    v1.x = expf(v1.x - m); v1.y = expf(v1.y - m); v1.z = expf(v1.z - m); v1.w = expf(v1.w - m);
    float s = v0.x + v0.y + v0.z + v0.w + v1.x + v1.y + v1.z + v1.w;
    #pragma unroll
    for (int o = 16; o; o >>= 1) s += __shfl_xor_sync(0xFFFFFFFFu, s, o);
    __syncthreads();
    if ((tid & 31) == 0) red[tid >> 5] = s;
    __syncthreads();
    if (tid == 0) {
        float ss = 0.0f;
        #pragma unroll
        for (int w = 0; w < 8; w++) ss += red[w];
        bcast = ss;
    }
    __syncthreads();
    float inv = 1.0f / bcast;
    v0.x *= inv; v0.y *= inv; v0.z *= inv; v0.w *= inv;
    v1.x *= inv; v1.y *= inv; v1.z *= inv; v1.w *= inv;
    Sr[tid] = v0;
    Sr[tid + 256] = v1;
}

// ---------------- launch ----------------------------------------------------
static float* sym_addr(const void* sym) {
    void* p = nullptr;
    cudaGetSymbolAddress(&p, sym);
    return (float*)p;
}

extern "C" void kernel_launch(void* const* d_in, const int* in_sizes, int n_in,
                              void* d_out, int out_size) {
    const float* x    = (const float*)d_in[0];
    const float* Wq   = (const float*)d_in[1];
    const float* Wk   = (const float*)d_in[2];
    const float* Wv   = (const float*)d_in[3];
    const float* Wrel = (const float*)d_in[4];
    const float* Wout = (const float*)d_in[5];
    const float* bout = (const float*)d_in[6];
    const float* rcb  = (const float*)d_in[7];
    const float* rpb  = (const float*)d_in[8];
    float* out = (float*)d_out;

    float* p_pos  = sym_addr(g_pos);
    float* p_relk = sym_addr(g_relk);
    float* p_q    = sym_addr(g_q);
    float* p_k    = sym_addr(g_k);
    float* p_v    = sym_addr(g_v);
    float* p_o    = sym_addr(g_o);
    float* p_S    = sym_addr(g_S);

    const int LOGITS_SMEM = (64 * QS_STRIDE + 64 * RS_STRIDE) * 4;  // 53248
    cudaFuncSetAttribute(logits_tf32, cudaFuncAttributeMaxDynamicSharedMemorySize,
                         LOGITS_SMEM);

    // 1. positional embedding
    pos_embed_kernel<<<LREL, 32>>>();

    // 2. rel_k = pos @ Wrel
    gemm_tf32<<<dim3(QKVW / 64, 32), 256>>>(p_pos, Wrel, nullptr, p_relk,
                                            LREL, FF, QKVW, FF, QKVW, QKVW, 0);

    // 3. q,k,v projections
    gemm_tf32<<<dim3(QKVW / 64, (BB * NN) / 128), 256>>>(x, Wq, nullptr, p_q,
                                                         BB * NN, DIMX, QKVW, DIMX, QKVW, QKVW, 0);
    gemm_tf32<<<dim3(QKVW / 64, (BB * NN) / 128), 256>>>(x, Wk, nullptr, p_k,
                                                         BB * NN, DIMX, QKVW, DIMX, QKVW, QKVW, 0);
    gemm_tf32<<<dim3(QKVW / 64, (BB * NN) / 128), 256>>>(x, Wv, nullptr, p_v,
                                                         BB * NN, DIMX, QKVW, DIMX, QKVW, QKVW, 0);

    // 4. logits (content + gathered rel)
    logits_tf32<<<dim3(NN / 64, NN / 64, BB * HH), 256, LOGITS_SMEM>>>(rcb, rpb);

    // 5. softmax
    softmax_kernel<<<BB * HH * NN, 256>>>();

    // 6. O = P @ V  (batched over bh)
    gemm_tf32<<<dim3(1, NN / 128, BB * HH), 256>>>(p_S, p_v, nullptr, p_o,
                                                   NN, NN, 64, NN, QKVW, QKVW, 1);

    // 7. out = O @ Wout + b_out
    gemm_tf32<<<dim3(DIMX / 64, (BB * NN) / 128), 256>>>(p_o, Wout, bout, out,
                                                         BB * NN, QKVW, DIMX, QKVW, DIMX, DIMX, 0);
}

// round 9
// speedup vs baseline: 1.4637x; 1.4637x over previous
#include <cuda_runtime.h>
#include <math.h>
#include <math_constants.h>
#include <stdint.h>

// Problem constants
#define BB 2
#define NN 2048
#define DIMX 768
#define HH 8
#define FF 192
#define LREL 4095            // 2*N - 1
#define QKVW 512             // H * DK

// ---------------- scratch (device globals; no allocation allowed) ----------
__device__ __align__(256) float g_pos[(size_t)LREL * FF];
__device__ __align__(256) float g_relk[(size_t)(LREL + 1) * QKVW]; // +1 pad row (stays 0)
__device__ __align__(256) float g_q[(size_t)BB * NN * QKVW];       // [b][n][h*64+d]
__device__ __align__(256) float g_k[(size_t)BB * NN * QKVW];
__device__ __align__(256) float g_v[(size_t)BB * NN * QKVW];
__device__ __align__(256) float g_o[(size_t)BB * NN * QKVW];

// ---------------- tf32 mma helpers -----------------------------------------
__device__ __forceinline__ uint32_t f2tf(float x) {
    uint32_t r; asm("cvt.rna.tf32.f32 %0, %1;" : "=r"(r) : "f"(x));
    return r;
}
__device__ __forceinline__ float tfv(float x) { return __uint_as_float(f2tf(x)); }
__device__ __forceinline__ void tfsplit(float x, uint32_t& hi, uint32_t& lo) {
    hi = f2tf(x);
    lo = f2tf(x - __uint_as_float(hi));
}
__device__ __forceinline__ void mma8(float* d, const uint32_t* a, const uint32_t* b) {
    asm volatile(
        "mma.sync.aligned.m16n8k8.row.col.f32.tf32.tf32.f32 "
        "{%0,%1,%2,%3},{%4,%5,%6,%7},{%8,%9},{%0,%1,%2,%3};\n"
        : "+f"(d[0]), "+f"(d[1]), "+f"(d[2]), "+f"(d[3])
        : "r"(a[0]), "r"(a[1]), "r"(a[2]), "r"(a[3]), "r"(b[0]), "r"(b[1]));
}
__device__ __forceinline__ void mma8x3(float* d, const uint32_t* ahi, const uint32_t* alo,
                                       const uint32_t* bhi, const uint32_t* blo) {
    mma8(d, ahi, blo);
    mma8(d, alo, bhi);
    mma8(d, ahi, bhi);
}
#define FU(x) __float_as_uint(x)

// ---------------- K1: positional embedding ----------------------------------
__global__ void pos_embed_kernel() {
    int row = blockIdx.x;
    int i = threadIdx.x;
    float dist = (float)(row - (NN - 1));
    float ad = fabsf(dist);

    float half_life = exp2f(3.0f + 8.0f * (float)i / 31.0f);
    float f_exp = exp2f(-ad / half_life);

    float width = exp2f((float)(i + 1)) - 1.0f;
    float f_cm = (width > ad) ? 1.0f : 0.0f;

    float mean = 64.0f * (float)(i + 1);
    float conc = (mean / 32.0f) * (mean / 32.0f);
    float rate = mean / 1024.0f;
    float log_unnorm = (conc - 1.0f) * logf(ad) - rate * ad;
    float log_norm = lgammaf(conc) - conc * logf(rate);
    float prob = expf(log_unnorm - log_norm) + 1e-8f;
    float pmax = prob;
    #pragma unroll
    for (int o = 16; o; o >>= 1) pmax = fmaxf(pmax, __shfl_xor_sync(0xFFFFFFFFu, pmax, o));
    float f_g = prob / pmax;

    float sgn = (dist > 0.0f) ? 1.0f : ((dist < 0.0f) ? -1.0f : 0.0f);

    float* out = g_pos + (size_t)row * FF;
    out[i]       = f_exp;
    out[32 + i]  = f_cm;
    out[64 + i]  = f_g;
    out[96 + i]  = sgn * f_exp;
    out[128 + i] = sgn * f_cm;
    out[160 + i] = sgn * f_g;
}

// ---------------- K2: generic tf32x3 GEMM (round-5, pvmode removed) --------
#define AS_STRIDE 136
#define BS_STRIDE 72
__global__ void gemm_tf32(const float* __restrict__ A, const float* __restrict__ B,
                          const float* __restrict__ bias, float* __restrict__ C,
                          int M, int K, int Nc, int lda, int ldb, int ldc) {
    __shared__ float As[32 * AS_STRIDE];
    __shared__ float Bs[32 * BS_STRIDE];

    int tid = threadIdx.x;
    int warp = tid >> 5, lane = tid & 31;
    int g = lane >> 2, tig = lane & 3;
    int mw = (warp >> 1) * 32, nw = (warp & 1) * 32;
    int m0 = blockIdx.y * 128, n0 = blockIdx.x * 64;

    float acc[2][4][4] = {};

    int arow = tid >> 3;
    int ak = (tid & 7) * 4;
    int bk = tid >> 3;
    int bn = (tid & 7) * 8;

    for (int k0 = 0; k0 < K; k0 += 32) {
        #pragma unroll
        for (int r = 0; r < 4; r++) {
            int ml = arow + 32 * r;
            int m = m0 + ml;
            float4 av = make_float4(0.f, 0.f, 0.f, 0.f);
            if (m < M) av = *(const float4*)(A + (size_t)m * lda + k0 + ak);
            As[(ak + 0) * AS_STRIDE + ml] = av.x;
            As[(ak + 1) * AS_STRIDE + ml] = av.y;
            As[(ak + 2) * AS_STRIDE + ml] = av.z;
            As[(ak + 3) * AS_STRIDE + ml] = av.w;
        }
        {
            const float* bp = B + (size_t)(k0 + bk) * ldb + n0 + bn;
            float4 b0 = *(const float4*)bp;
            float4 b1 = *(const float4*)(bp + 4);
            Bs[bk * BS_STRIDE + bn + 0] = b0.x;
            Bs[bk * BS_STRIDE + bn + 1] = b0.y;
            Bs[bk * BS_STRIDE + bn + 2] = b0.z;
            Bs[bk * BS_STRIDE + bn + 3] = b0.w;
            Bs[bk * BS_STRIDE + bn + 4] = b1.x;
            Bs[bk * BS_STRIDE + bn + 5] = b1.y;
            Bs[bk * BS_STRIDE + bn + 6] = b1.z;
            Bs[bk * BS_STRIDE + bn + 7] = b1.w;
        }
        __syncthreads();
        #pragma unroll
        for (int kk = 0; kk < 32; kk += 8) {
            uint32_t ah[2][4], al[2][4];
            #pragma unroll
            for (int f = 0; f < 2; f++) {
                int mb = mw + 16 * f;
                tfsplit(As[(kk + tig) * AS_STRIDE + mb + g],         ah[f][0], al[f][0]);
                tfsplit(As[(kk + tig) * AS_STRIDE + mb + g + 8],     ah[f][1], al[f][1]);
                tfsplit(As[(kk + tig + 4) * AS_STRIDE + mb + g],     ah[f][2], al[f][2]);
                tfsplit(As[(kk + tig + 4) * AS_STRIDE + mb + g + 8], ah[f][3], al[f][3]);
            }
            #pragma unroll
            for (int j = 0; j < 4; j++) {
                uint32_t bh2[2], bl2[2];
                tfsplit(Bs[(kk + tig) * BS_STRIDE + nw + 8 * j + g],     bh2[0], bl2[0]);
                tfsplit(Bs[(kk + tig + 4) * BS_STRIDE + nw + 8 * j + g], bh2[1], bl2[1]);
                mma8x3(acc[0][j], ah[0], al[0], bh2, bl2);
                mma8x3(acc[1][j], ah[1], al[1], bh2, bl2);
            }
        }
        __syncthreads();
    }

    #pragma unroll
    for (int f = 0; f < 2; f++) {
        #pragma unroll
        for (int j = 0; j < 4; j++) {
            int n = n0 + nw + 8 * j + 2 * tig;
            float b0v = bias ? bias[n] : 0.0f;
            float b1v = bias ? bias[n + 1] : 0.0f;
            int m = m0 + mw + 16 * f + g;
            if (m < M)
                *(float2*)(C + (size_t)m * ldc + n) =
                    make_float2(acc[f][j][0] + b0v, acc[f][j][1] + b1v);
            if (m + 8 < M)
                *(float2*)(C + (size_t)(m + 8) * ldc + n) =
                    make_float2(acc[f][j][2] + b0v, acc[f][j][3] + b1v);
        }
    }
}

// ---------------- K3: fused attention ---------------------------------------
// Per block: 64 query rows (i0) x one (b,h). Streams 32 j-tiles of 64.
// k4-grouped smem layout: elem (k,m) at (k>>2)*260 + 4*m + (k&3).
// smem float offsets:
#define SQCH 0
#define SQCL 4160
#define SQPH 8320
#define SQPL 12480
#define SRSH 16640
#define SRSL 20800
#define SVS  24960
#define SPSH 29120
#define SPSL 33280
#define SGB  37440      // 2 slots x 64 rows x 68
#define SRED 46144      // redm[128]
#define SRES 46272      // reds[128]
#define SM_TOT 46400
#define GSLOT 4352

// split-load a 64x64 tile (rows x 64 dims, ld=512) into k4 hi/lo (dest[(d,row)])
__device__ __forceinline__ void ld_split(const float* src, float* dh, float* dl, int tid) {
    int row = tid & 63, dg = tid >> 6;
    #pragma unroll
    for (int r = 0; r < 4; r++) {
        int grp = dg + 4 * r;
        float4 v = *(const float4*)(src + (size_t)row * QKVW + grp * 4);
        float h0 = tfv(v.x), h1 = tfv(v.y), h2 = tfv(v.z), h3 = tfv(v.w);
        *(float4*)&dh[grp * 260 + row * 4] = make_float4(h0, h1, h2, h3);
        *(float4*)&dl[grp * 260 + row * 4] = make_float4(v.x - h0, v.y - h1, v.z - h2, v.w - h3);
    }
}
// Q loader: (q*0.125 + bias64) then split
__device__ __forceinline__ void ld_split_q(const float* src, const float* bias64,
                                           float* dh, float* dl, int tid) {
    int row = tid & 63, dg = tid >> 6;
    #pragma unroll
    for (int r = 0; r < 4; r++) {
        int grp = dg + 4 * r;
        float4 v = *(const float4*)(src + (size_t)row * QKVW + grp * 4);
        float4 bb = *(const float4*)(bias64 + grp * 4);
        float c0 = v.x * 0.125f + bb.x, c1 = v.y * 0.125f + bb.y;
        float c2 = v.z * 0.125f + bb.z, c3 = v.w * 0.125f + bb.w;
        float h0 = tfv(c0), h1 = tfv(c1), h2 = tfv(c2), h3 = tfv(c3);
        *(float4*)&dh[grp * 260 + row * 4] = make_float4(h0, h1, h2, h3);
        *(float4*)&dl[grp * 260 + row * 4] = make_float4(c0 - h0, c1 - h1, c2 - h2, c3 - h3);
    }
}
// V loader: transpose into B-operand k4 (k = j-row, n = dv), rna-rounded
__device__ __forceinline__ void ld_v(const float* src, float* dv, int tid) {
    int row = tid & 63, dg = tid >> 6;
    #pragma unroll
    for (int r = 0; r < 4; r++) {
        int grp = dg + 4 * r;
        float4 v = *(const float4*)(src + (size_t)row * QKVW + grp * 4);
        int bb = (row >> 2) * 260 + (row & 3);
        dv[bb + (grp * 4 + 0) * 4] = tfv(v.x);
        dv[bb + (grp * 4 + 1) * 4] = tfv(v.y);
        dv[bb + (grp * 4 + 2) * 4] = tfv(v.z);
        dv[bb + (grp * 4 + 3) * 4] = tfv(v.w);
    }
}

__global__ __launch_bounds__(256, 1) void attn_fused(const float* __restrict__ rcb,
                                                     const float* __restrict__ rpb) {
    extern __shared__ float sm[];
    float* redm = sm + SRED;
    float* reds = sm + SRES;

    int bhid = blockIdx.y;
    int b = bhid >> 3, h = bhid & 7;
    int i0 = blockIdx.x * 64;
    int tid = threadIdx.x, warp = tid >> 5, lane = tid & 31;
    int g = lane >> 2, tig = lane & 3;
    int mwl = (warp >> 1) * 16, nwl = (warp & 1) * 32;
    int li0 = mwl + g, li1 = li0 + 8;

    const float* qb = g_q + (size_t)b * NN * QKVW + h * 64;
    const float* kb = g_k + (size_t)b * NN * QKVW + h * 64;
    const float* vb = g_v + (size_t)b * NN * QKVW + h * 64;
    const float* rkb = g_relk + h * 64;

    // prologue: Q tiles (content & pos), band chunk 0
    ld_split_q(qb + (size_t)i0 * QKVW, rcb + h * 64, sm + SQCH, sm + SQCL, tid);
    ld_split_q(qb + (size_t)i0 * QKVW, rpb + h * 64, sm + SQPH, sm + SQPL, tid);
    int relbase = 1984 - i0;   // chunk c covers relk rows [relbase + 64c, +64)
    ld_split(g_relk + (size_t)relbase * QKVW + h * 64, sm + SRSH, sm + SRSL, tid);
    __syncthreads();
    // G chunk 0 -> Gbuf slot 0
    {
        float gacc[4][4] = {};
        #pragma unroll
        for (int kk = 0; kk < 64; kk += 8) {
            int q0 = (kk >> 2) * 260, q1 = q0 + 260;
            int ma = 4 * li0 + tig, mb = ma + 32;
            uint32_t ah[4], al[4];
            ah[0] = FU(sm[SQPH + q0 + ma]); ah[1] = FU(sm[SQPH + q0 + mb]);
            ah[2] = FU(sm[SQPH + q1 + ma]); ah[3] = FU(sm[SQPH + q1 + mb]);
            al[0] = FU(sm[SQPL + q0 + ma]); al[1] = FU(sm[SQPL + q0 + mb]);
            al[2] = FU(sm[SQPL + q1 + ma]); al[3] = FU(sm[SQPL + q1 + mb]);
            #pragma unroll
            for (int j = 0; j < 4; j++) {
                int nb = 4 * (nwl + 8 * j + g) + tig;
                uint32_t bh2[2] = { FU(sm[SRSH + q0 + nb]), FU(sm[SRSH + q1 + nb]) };
                uint32_t bl2[2] = { FU(sm[SRSL + q0 + nb]), FU(sm[SRSL + q1 + nb]) };
                mma8x3(gacc[j], ah, al, bh2, bl2);
            }
        }
        float* Gb = sm + SGB;
        #pragma unroll
        for (int j = 0; j < 4; j++) {
            int c = nwl + 8 * j + 2 * tig;
            *(float2*)&Gb[li0 * 68 + c] = make_float2(gacc[j][0], gacc[j][1]);
            *(float2*)&Gb[li1 * 68 + c] = make_float2(gacc[j][2], gacc[j][3]);
        }
    }

    float oacc[4][4] = {};
    float m0r = -CUDART_INF_F, m1r = -CUDART_INF_F;
    float l0 = 0.0f, l1 = 0.0f;

    for (int t = 0; t < 32; t++) {
        __syncthreads();   // S1: prev PV / prologue done
        ld_split(kb + (size_t)t * 64 * QKVW, sm + SRSH, sm + SRSL, tid);
        ld_v(vb + (size_t)t * 64 * QKVW, sm + SVS, tid);
        __syncthreads();   // S2

        // content mma
        float cacc[4][4] = {};
        #pragma unroll
        for (int kk = 0; kk < 64; kk += 8) {
            int q0 = (kk >> 2) * 260, q1 = q0 + 260;
            int ma = 4 * li0 + tig, mb = ma + 32;
            uint32_t ah[4], al[4];
            ah[0] = FU(sm[SQCH + q0 + ma]); ah[1] = FU(sm[SQCH + q0 + mb]);
            ah[2] = FU(sm[SQCH + q1 + ma]); ah[3] = FU(sm[SQCH + q1 + mb]);
            al[0] = FU(sm[SQCL + q0 + ma]); al[1] = FU(sm[SQCL + q0 + mb]);
            al[2] = FU(sm[SQCL + q1 + ma]); al[3] = FU(sm[SQCL + q1 + mb]);
            #pragma unroll
            for (int j = 0; j < 4; j++) {
                int nb = 4 * (nwl + 8 * j + g) + tig;
                uint32_t bh2[2] = { FU(sm[SRSH + q0 + nb]), FU(sm[SRSH + q1 + nb]) };
                uint32_t bl2[2] = { FU(sm[SRSL + q0 + nb]), FU(sm[SRSL + q1 + nb]) };
                mma8x3(cacc[j], ah, al, bh2, bl2);
            }
        }
        __syncthreads();   // S3: Rs free

        // band chunk t+1
        ld_split(g_relk + (size_t)(relbase + 64 * (t + 1)) * QKVW + h * 64,
                 sm + SRSH, sm + SRSL, tid);
        __syncthreads();   // S4

        // G mma -> Gbuf[(t+1)&1]
        {
            float gacc[4][4] = {};
            #pragma unroll
            for (int kk = 0; kk < 64; kk += 8) {
                int q0 = (kk >> 2) * 260, q1 = q0 + 260;
                int ma = 4 * li0 + tig, mb = ma + 32;
                uint32_t ah[4], al[4];
                ah[0] = FU(sm[SQPH + q0 + ma]); ah[1] = FU(sm[SQPH + q0 + mb]);
                ah[2] = FU(sm[SQPH + q1 + ma]); ah[3] = FU(sm[SQPH + q1 + mb]);
                al[0] = FU(sm[SQPL + q0 + ma]); al[1] = FU(sm[SQPL + q0 + mb]);
                al[2] = FU(sm[SQPL + q1 + ma]); al[3] = FU(sm[SQPL + q1 + mb]);
                #pragma unroll
                for (int j = 0; j < 4; j++) {
                    int nb = 4 * (nwl + 8 * j + g) + tig;
                    uint32_t bh2[2] = { FU(sm[SRSH + q0 + nb]), FU(sm[SRSH + q1 + nb]) };
                    uint32_t bl2[2] = { FU(sm[SRSL + q0 + nb]), FU(sm[SRSL + q1 + nb]) };
                    mma8x3(gacc[j], ah, al, bh2, bl2);
                }
            }
            float* Gb = sm + SGB + ((t + 1) & 1) * GSLOT;
            #pragma unroll
            for (int j = 0; j < 4; j++) {
                int c = nwl + 8 * j + 2 * tig;
                *(float2*)&Gb[li0 * 68 + c] = make_float2(gacc[j][0], gacc[j][1]);
                *(float2*)&Gb[li1 * 68 + c] = make_float2(gacc[j][2], gacc[j][3]);
            }
        }
        __syncthreads();   // S5: Gbuf visible

        // gather + rowmax
        const float* G0 = sm + SGB + (t & 1) * GSLOT;
        const float* G1 = sm + SGB + ((t + 1) & 1) * GSLOT;
        float s0[8], s1[8];
        float rm0 = -CUDART_INF_F, rm1 = -CUDART_INF_F;
        #pragma unroll
        for (int j = 0; j < 4; j++) {
            #pragma unroll
            for (int e = 0; e < 2; e++) {
                int lj = nwl + 8 * j + 2 * tig + e;
                int rl0 = lj - li0 + 63;
                int rl1 = lj - li1 + 63;
                float gv0 = (rl0 < 64) ? G0[li0 * 68 + rl0] : G1[li0 * 68 + rl0 - 64];
                float gv1 = (rl1 < 64) ? G0[li1 * 68 + rl1] : G1[li1 * 68 + rl1 - 64];
                float v0 = cacc[j][e]     + gv0;
                float v1 = cacc[j][2 + e] + gv1;
                s0[2 * j + e] = v0; s1[2 * j + e] = v1;
                rm0 = fmaxf(rm0, v0); rm1 = fmaxf(rm1, v1);
            }
        }
        rm0 = fmaxf(rm0, __shfl_xor_sync(0xFFFFFFFFu, rm0, 1));
        rm0 = fmaxf(rm0, __shfl_xor_sync(0xFFFFFFFFu, rm0, 2));
        rm1 = fmaxf(rm1, __shfl_xor_sync(0xFFFFFFFFu, rm1, 1));
        rm1 = fmaxf(rm1, __shfl_xor_sync(0xFFFFFFFFu, rm1, 2));
        if (tig == 0) {
            redm[(warp & 1) * 64 + li0] = rm0;
            redm[(warp & 1) * 64 + li1] = rm1;
        }
        __syncthreads();   // S6

        float mn0 = fmaxf(m0r, fmaxf(redm[li0], redm[64 + li0]));
        float mn1 = fmaxf(m1r, fmaxf(redm[li1], redm[64 + li1]));
        float sc0 = expf(m0r - mn0), sc1 = expf(m1r - mn1);
        m0r = mn0; m1r = mn1;
        float rs0 = 0.0f, rs1 = 0.0f;
        #pragma unroll
        for (int j = 0; j < 4; j++) {
            oacc[j][0] *= sc0; oacc[j][1] *= sc0;
            oacc[j][2] *= sc1; oacc[j][3] *= sc1;
            float p0a = expf(s0[2 * j] - mn0),     p0b = expf(s0[2 * j + 1] - mn0);
            float p1a = expf(s1[2 * j] - mn1),     p1b = expf(s1[2 * j + 1] - mn1);
            rs0 += p0a + p0b; rs1 += p1a + p1b;
            int c = nwl + 8 * j + 2 * tig;
            int base = (c >> 2) * 260 + (c & 3);
            float h0a = tfv(p0a), h0b = tfv(p0b), h1a = tfv(p1a), h1b = tfv(p1b);
            *(float2*)&sm[SPSH + base + 4 * li0] = make_float2(h0a, h0b);
            *(float2*)&sm[SPSH + base + 4 * li1] = make_float2(h1a, h1b);
            *(float2*)&sm[SPSL + base + 4 * li0] = make_float2(p0a - h0a, p0b - h0b);
            *(float2*)&sm[SPSL + base + 4 * li1] = make_float2(p1a - h1a, p1b - h1b);
        }
        rs0 += __shfl_xor_sync(0xFFFFFFFFu, rs0, 1);
        rs0 += __shfl_xor_sync(0xFFFFFFFFu, rs0, 2);
        rs1 += __shfl_xor_sync(0xFFFFFFFFu, rs1, 1);
        rs1 += __shfl_xor_sync(0xFFFFFFFFu, rs1, 2);
        if (tig == 0) {
            reds[(warp & 1) * 64 + li0] = rs0;
            reds[(warp & 1) * 64 + li1] = rs1;
        }
        __syncthreads();   // S7

        l0 = l0 * sc0 + reds[li0] + reds[64 + li0];
        l1 = l1 * sc1 + reds[li1] + reds[64 + li1];

        // PV mma (x2 on P, V rna)
        #pragma unroll
        for (int kk = 0; kk < 64; kk += 8) {
            int q0 = (kk >> 2) * 260, q1 = q0 + 260;
            int ma = 4 * li0 + tig, mb = ma + 32;
            uint32_t ph[4], pl[4];
            ph[0] = FU(sm[SPSH + q0 + ma]); ph[1] = FU(sm[SPSH + q0 + mb]);
            ph[2] = FU(sm[SPSH + q1 + ma]); ph[3] = FU(sm[SPSH + q1 + mb]);
            pl[0] = FU(sm[SPSL + q0 + ma]); pl[1] = FU(sm[SPSL + q0 + mb]);
            pl[2] = FU(sm[SPSL + q1 + ma]); pl[3] = FU(sm[SPSL + q1 + mb]);
            #pragma unroll
            for (int j = 0; j < 4; j++) {
                int nb = 4 * (nwl + 8 * j + g) + tig;
                uint32_t bf[2] = { FU(sm[SVS + q0 + nb]), FU(sm[SVS + q1 + nb]) };
                mma8(oacc[j], ph, bf);
                mma8(oacc[j], pl, bf);
            }
        }
    }

    float inv0 = 1.0f / l0, inv1 = 1.0f / l1;
    float* ob = g_o + (size_t)(b * NN + i0) * QKVW + h * 64;
    #pragma unroll
    for (int j = 0; j < 4; j++) {
        int c = nwl + 8 * j + 2 * tig;
        *(float2*)(ob + (size_t)li0 * QKVW + c) =
            make_float2(oacc[j][0] * inv0, oacc[j][1] * inv0);
        *(float2*)(ob + (size_t)li1 * QKVW + c) =
            make_float2(oacc[j][2] * inv1, oacc[j][3] * inv1);
    }
}

// ---------------- launch ----------------------------------------------------
static float* sym_addr(const void* sym) {
    void* p = nullptr;
    cudaGetSymbolAddress(&p, sym);
    return (float*)p;
}

extern "C" void kernel_launch(void* const* d_in, const int* in_sizes, int n_in,
                              void* d_out, int out_size) {
    const float* x    = (const float*)d_in[0];
    const float* Wq   = (const float*)d_in[1];
    const float* Wk   = (const float*)d_in[2];
    const float* Wv   = (const float*)d_in[3];
    const float* Wrel = (const float*)d_in[4];
    const float* Wout = (const float*)d_in[5];
    const float* bout = (const float*)d_in[6];
    const float* rcb  = (const float*)d_in[7];
    const float* rpb  = (const float*)d_in[8];
    float* out = (float*)d_out;

    float* p_pos  = sym_addr(g_pos);
    float* p_relk = sym_addr(g_relk);
    float* p_q    = sym_addr(g_q);
    float* p_k    = sym_addr(g_k);
    float* p_v    = sym_addr(g_v);
    float* p_o    = sym_addr(g_o);

    const int FUSED_SMEM = SM_TOT * 4;   // 185,600 B
    cudaFuncSetAttribute(attn_fused, cudaFuncAttributeMaxDynamicSharedMemorySize,
                         FUSED_SMEM);

    // 1. positional embedding
    pos_embed_kernel<<<LREL, 32>>>();

    // 2. rel_k = pos @ Wrel  (row 4095 of g_relk stays 0 = pad)
    gemm_tf32<<<dim3(QKVW / 64, 32), 256>>>(p_pos, Wrel, nullptr, p_relk,
                                            LREL, FF, QKVW, FF, QKVW, QKVW);

    // 3. q,k,v projections
    gemm_tf32<<<dim3(QKVW / 64, (BB * NN) / 128), 256>>>(x, Wq, nullptr, p_q,
                                                         BB * NN, DIMX, QKVW, DIMX, QKVW, QKVW);
    gemm_tf32<<<dim3(QKVW / 64, (BB * NN) / 128), 256>>>(x, Wk, nullptr, p_k,
                                                         BB * NN, DIMX, QKVW, DIMX, QKVW, QKVW);
    gemm_tf32<<<dim3(QKVW / 64, (BB * NN) / 128), 256>>>(x, Wv, nullptr, p_v,
                                                         BB * NN, DIMX, QKVW, DIMX, QKVW, QKVW);

    // 4. fused logits + online softmax + P@V
    attn_fused<<<dim3(NN / 64, BB * HH), 256, FUSED_SMEM>>>(rcb, rpb);

    // 5. out = O @ Wout + b_out
    gemm_tf32<<<dim3(DIMX / 64, (BB * NN) / 128), 256>>>(p_o, Wout, bout, out,
                                                         BB * NN, QKVW, DIMX, QKVW, DIMX, DIMX);
}

// round 10
// speedup vs baseline: 1.5314x; 1.0462x over previous
#include <cuda_runtime.h>
#include <math.h>
#include <math_constants.h>
#include <stdint.h>

// Problem constants
#define BB 2
#define NN 2048
#define DIMX 768
#define HH 8
#define FF 192
#define LREL 4095            // 2*N - 1
#define QKVW 512             // H * DK

// ---------------- scratch (device globals; no allocation allowed) ----------
__device__ __align__(256) float g_pos[(size_t)LREL * FF];
__device__ __align__(256) float g_relk[(size_t)(LREL + 1) * QKVW]; // +1 pad row (stays 0)
__device__ __align__(256) float g_q[(size_t)BB * NN * QKVW];       // [b][n][h*64+d]
__device__ __align__(256) float g_k[(size_t)BB * NN * QKVW];
__device__ __align__(256) float g_v[(size_t)BB * NN * QKVW];
__device__ __align__(256) float g_o[(size_t)BB * NN * QKVW];

// ---------------- tf32 mma helpers -----------------------------------------
__device__ __forceinline__ uint32_t f2tf(float x) {
    uint32_t r; asm("cvt.rna.tf32.f32 %0, %1;" : "=r"(r) : "f"(x));
    return r;
}
__device__ __forceinline__ float tfv(float x) { return __uint_as_float(f2tf(x)); }
__device__ __forceinline__ void mma8(float* d, const uint32_t* a, const uint32_t* b) {
    asm volatile(
        "mma.sync.aligned.m16n8k8.row.col.f32.tf32.tf32.f32 "
        "{%0,%1,%2,%3},{%4,%5,%6,%7},{%8,%9},{%0,%1,%2,%3};\n"
        : "+f"(d[0]), "+f"(d[1]), "+f"(d[2]), "+f"(d[3])
        : "r"(a[0]), "r"(a[1]), "r"(a[2]), "r"(a[3]), "r"(b[0]), "r"(b[1]));
}
__device__ __forceinline__ void mma8x3(float* d, const uint32_t* ahi, const uint32_t* alo,
                                       const uint32_t* bhi, const uint32_t* blo) {
    mma8(d, ahi, blo);
    mma8(d, alo, bhi);
    mma8(d, ahi, bhi);
}
#define FU(x) __float_as_uint(x)

// ---------------- K1: positional embedding ----------------------------------
__global__ void pos_embed_kernel() {
    int row = blockIdx.x;
    int i = threadIdx.x;
    float dist = (float)(row - (NN - 1));
    float ad = fabsf(dist);

    float half_life = exp2f(3.0f + 8.0f * (float)i / 31.0f);
    float f_exp = exp2f(-ad / half_life);

    float width = exp2f((float)(i + 1)) - 1.0f;
    float f_cm = (width > ad) ? 1.0f : 0.0f;

    float mean = 64.0f * (float)(i + 1);
    float conc = (mean / 32.0f) * (mean / 32.0f);
    float rate = mean / 1024.0f;
    float log_unnorm = (conc - 1.0f) * logf(ad) - rate * ad;
    float log_norm = lgammaf(conc) - conc * logf(rate);
    float prob = expf(log_unnorm - log_norm) + 1e-8f;
    float pmax = prob;
    #pragma unroll
    for (int o = 16; o; o >>= 1) pmax = fmaxf(pmax, __shfl_xor_sync(0xFFFFFFFFu, pmax, o));
    float f_g = prob / pmax;

    float sgn = (dist > 0.0f) ? 1.0f : ((dist < 0.0f) ? -1.0f : 0.0f);

    float* out = g_pos + (size_t)row * FF;
    out[i]       = f_exp;
    out[32 + i]  = f_cm;
    out[64 + i]  = f_g;
    out[96 + i]  = sgn * f_exp;
    out[128 + i] = sgn * f_cm;
    out[160 + i] = sgn * f_g;
}

// ---------------- K2: tf32x3 GEMM v2 — split-at-store, k4 layout ------------
// C[M,Nc] = A[M,K] @ B[K,Nc] (+bias). Block tile 128x64, 8 warps, k-step 32.
// Optional second/third B&C (selected by blockIdx.z) for fused q/k/v.
// Layout: elem (k,m) at (k>>2)*G + 4*m + (k&3);  GA=516 (m:128), GB=260 (n:64).
#define GA 516
#define GB 260
#define VAH 0
#define VAL 4128
#define VBH 8256
#define VBL 10336
#define GEMM_SMEM ((10336 + 2080) * 4)    // 49,664 B
__global__ __launch_bounds__(256) void gemm_tf32(
    const float* __restrict__ A, const float* __restrict__ B0,
    const float* __restrict__ B1, const float* __restrict__ B2,
    const float* __restrict__ bias, float* __restrict__ C0,
    float* __restrict__ C1, float* __restrict__ C2,
    int M, int K, int Nc, int lda, int ldb, int ldc) {
    extern __shared__ float sg[];
    float* sAh = sg + VAH; float* sAl = sg + VAL;
    float* sBh = sg + VBH; float* sBl = sg + VBL;

    const float* B = B0;
    float* C = C0;
    if (blockIdx.z == 1) { B = B1; C = C1; }
    else if (blockIdx.z == 2) { B = B2; C = C2; }

    int tid = threadIdx.x;
    int warp = tid >> 5, lane = tid & 31;
    int g = lane >> 2, tig = lane & 3;
    int mw = (warp >> 1) * 32, nw = (warp & 1) * 32;
    int m0 = blockIdx.y * 128, n0 = blockIdx.x * 64;

    float acc[2][4][4] = {};

    int am = tid & 127, akg0 = tid >> 7;   // A: kg = akg0 + 2r (r=0..3)
    int bn = tid & 63,  bkg0 = tid >> 6;   // B: kg = bkg0 + 4r (r=0..1)

    for (int k0 = 0; k0 < K; k0 += 32) {
        #pragma unroll
        for (int r = 0; r < 4; r++) {
            int kg = akg0 + 2 * r;
            int m = m0 + am;
            float4 v = make_float4(0.f, 0.f, 0.f, 0.f);
            if (m < M) v = *(const float4*)(A + (size_t)m * lda + k0 + kg * 4);
            float h0 = tfv(v.x), h1 = tfv(v.y), h2 = tfv(v.z), h3 = tfv(v.w);
            *(float4*)&sAh[kg * GA + am * 4] = make_float4(h0, h1, h2, h3);
            *(float4*)&sAl[kg * GA + am * 4] =
                make_float4(v.x - h0, v.y - h1, v.z - h2, v.w - h3);
        }
        #pragma unroll
        for (int r = 0; r < 2; r++) {
            int kg = bkg0 + 4 * r;
            const float* bp = B + (size_t)(k0 + kg * 4) * ldb + n0 + bn;
            float x0 = bp[0];
            float x1 = bp[(size_t)ldb];
            float x2 = bp[2 * (size_t)ldb];
            float x3 = bp[3 * (size_t)ldb];
            float h0 = tfv(x0), h1 = tfv(x1), h2 = tfv(x2), h3 = tfv(x3);
            *(float4*)&sBh[kg * GB + bn * 4] = make_float4(h0, h1, h2, h3);
            *(float4*)&sBl[kg * GB + bn * 4] =
                make_float4(x0 - h0, x1 - h1, x2 - h2, x3 - h3);
        }
        __syncthreads();
        #pragma unroll
        for (int kk = 0; kk < 32; kk += 8) {
            int qa = (kk >> 2) * GA, qb2 = (kk >> 2) * GB;
            uint32_t ah[2][4], al[2][4], bhf[4][2], blf[4][2];
            #pragma unroll
            for (int f = 0; f < 2; f++) {
                int ma = (mw + 16 * f + g) * 4 + tig;
                ah[f][0] = FU(sAh[qa + ma]);
                ah[f][1] = FU(sAh[qa + ma + 32]);
                ah[f][2] = FU(sAh[qa + GA + ma]);
                ah[f][3] = FU(sAh[qa + GA + ma + 32]);
                al[f][0] = FU(sAl[qa + ma]);
                al[f][1] = FU(sAl[qa + ma + 32]);
                al[f][2] = FU(sAl[qa + GA + ma]);
                al[f][3] = FU(sAl[qa + GA + ma + 32]);
            }
            #pragma unroll
            for (int j = 0; j < 4; j++) {
                int nb = (nw + 8 * j + g) * 4 + tig;
                bhf[j][0] = FU(sBh[qb2 + nb]);
                bhf[j][1] = FU(sBh[qb2 + GB + nb]);
                blf[j][0] = FU(sBl[qb2 + nb]);
                blf[j][1] = FU(sBl[qb2 + GB + nb]);
            }
            #pragma unroll
            for (int f = 0; f < 2; f++)
                #pragma unroll
                for (int j = 0; j < 4; j++) mma8(acc[f][j], ah[f], bhf[j]);
            #pragma unroll
            for (int f = 0; f < 2; f++)
                #pragma unroll
                for (int j = 0; j < 4; j++) mma8(acc[f][j], ah[f], blf[j]);
            #pragma unroll
            for (int f = 0; f < 2; f++)
                #pragma unroll
                for (int j = 0; j < 4; j++) mma8(acc[f][j], al[f], bhf[j]);
        }
        __syncthreads();
    }

    #pragma unroll
    for (int f = 0; f < 2; f++) {
        #pragma unroll
        for (int j = 0; j < 4; j++) {
            int n = n0 + nw + 8 * j + 2 * tig;
            float b0v = bias ? bias[n] : 0.0f;
            float b1v = bias ? bias[n + 1] : 0.0f;
            int m = m0 + mw + 16 * f + g;
            if (m < M)
                *(float2*)(C + (size_t)m * ldc + n) =
                    make_float2(acc[f][j][0] + b0v, acc[f][j][1] + b1v);
            if (m + 8 < M)
                *(float2*)(C + (size_t)(m + 8) * ldc + n) =
                    make_float2(acc[f][j][2] + b0v, acc[f][j][3] + b1v);
        }
    }
}

// ---------------- K3: fused attention (unchanged from round 8) --------------
#define SQCH 0
#define SQCL 4160
#define SQPH 8320
#define SQPL 12480
#define SRSH 16640
#define SRSL 20800
#define SVS  24960
#define SPSH 29120
#define SPSL 33280
#define SGB  37440      // 2 slots x 64 rows x 68
#define SRED 46144
#define SRES 46272
#define SM_TOT 46400
#define GSLOT 4352

__device__ __forceinline__ void ld_split(const float* src, float* dh, float* dl, int tid) {
    int row = tid & 63, dg = tid >> 6;
    #pragma unroll
    for (int r = 0; r < 4; r++) {
        int grp = dg + 4 * r;
        float4 v = *(const float4*)(src + (size_t)row * QKVW + grp * 4);
        float h0 = tfv(v.x), h1 = tfv(v.y), h2 = tfv(v.z), h3 = tfv(v.w);
        *(float4*)&dh[grp * 260 + row * 4] = make_float4(h0, h1, h2, h3);
        *(float4*)&dl[grp * 260 + row * 4] = make_float4(v.x - h0, v.y - h1, v.z - h2, v.w - h3);
    }
}
__device__ __forceinline__ void ld_split_q(const float* src, const float* bias64,
                                           float* dh, float* dl, int tid) {
    int row = tid & 63, dg = tid >> 6;
    #pragma unroll
    for (int r = 0; r < 4; r++) {
        int grp = dg + 4 * r;
        float4 v = *(const float4*)(src + (size_t)row * QKVW + grp * 4);
        float4 bb = *(const float4*)(bias64 + grp * 4);
        float c0 = v.x * 0.125f + bb.x, c1 = v.y * 0.125f + bb.y;
        float c2 = v.z * 0.125f + bb.z, c3 = v.w * 0.125f + bb.w;
        float h0 = tfv(c0), h1 = tfv(c1), h2 = tfv(c2), h3 = tfv(c3);
        *(float4*)&dh[grp * 260 + row * 4] = make_float4(h0, h1, h2, h3);
        *(float4*)&dl[grp * 260 + row * 4] = make_float4(c0 - h0, c1 - h1, c2 - h2, c3 - h3);
    }
}
__device__ __forceinline__ void ld_v(const float* src, float* dv, int tid) {
    int row = tid & 63, dg = tid >> 6;
    #pragma unroll
    for (int r = 0; r < 4; r++) {
        int grp = dg + 4 * r;
        float4 v = *(const float4*)(src + (size_t)row * QKVW + grp * 4);
        int bb = (row >> 2) * 260 + (row & 3);
        dv[bb + (grp * 4 + 0) * 4] = tfv(v.x);
        dv[bb + (grp * 4 + 1) * 4] = tfv(v.y);
        dv[bb + (grp * 4 + 2) * 4] = tfv(v.z);
        dv[bb + (grp * 4 + 3) * 4] = tfv(v.w);
    }
}

__global__ __launch_bounds__(256, 1) void attn_fused(const float* __restrict__ rcb,
                                                     const float* __restrict__ rpb) {
    extern __shared__ float sm[];
    float* redm = sm + SRED;
    float* reds = sm + SRES;

    int bhid = blockIdx.y;
    int b = bhid >> 3, h = bhid & 7;
    int i0 = blockIdx.x * 64;
    int tid = threadIdx.x, warp = tid >> 5, lane = tid & 31;
    int g = lane >> 2, tig = lane & 3;
    int mwl = (warp >> 1) * 16, nwl = (warp & 1) * 32;
    int li0 = mwl + g, li1 = li0 + 8;

    const float* qb = g_q + (size_t)b * NN * QKVW + h * 64;
    const float* kb = g_k + (size_t)b * NN * QKVW + h * 64;
    const float* vb = g_v + (size_t)b * NN * QKVW + h * 64;

    ld_split_q(qb + (size_t)i0 * QKVW, rcb + h * 64, sm + SQCH, sm + SQCL, tid);
    ld_split_q(qb + (size_t)i0 * QKVW, rpb + h * 64, sm + SQPH, sm + SQPL, tid);
    int relbase = 1984 - i0;
    ld_split(g_relk + (size_t)relbase * QKVW + h * 64, sm + SRSH, sm + SRSL, tid);
    __syncthreads();
    {
        float gacc[4][4] = {};
        #pragma unroll
        for (int kk = 0; kk < 64; kk += 8) {
            int q0 = (kk >> 2) * 260, q1 = q0 + 260;
            int ma = 4 * li0 + tig, mb = ma + 32;
            uint32_t ah[4], al[4];
            ah[0] = FU(sm[SQPH + q0 + ma]); ah[1] = FU(sm[SQPH + q0 + mb]);
            ah[2] = FU(sm[SQPH + q1 + ma]); ah[3] = FU(sm[SQPH + q1 + mb]);
            al[0] = FU(sm[SQPL + q0 + ma]); al[1] = FU(sm[SQPL + q0 + mb]);
            al[2] = FU(sm[SQPL + q1 + ma]); al[3] = FU(sm[SQPL + q1 + mb]);
            #pragma unroll
            for (int j = 0; j < 4; j++) {
                int nb = 4 * (nwl + 8 * j + g) + tig;
                uint32_t bh2[2] = { FU(sm[SRSH + q0 + nb]), FU(sm[SRSH + q1 + nb]) };
                uint32_t bl2[2] = { FU(sm[SRSL + q0 + nb]), FU(sm[SRSL + q1 + nb]) };
                mma8x3(gacc[j], ah, al, bh2, bl2);
            }
        }
        float* Gb = sm + SGB;
        #pragma unroll
        for (int j = 0; j < 4; j++) {
            int c = nwl + 8 * j + 2 * tig;
            *(float2*)&Gb[li0 * 68 + c] = make_float2(gacc[j][0], gacc[j][1]);
            *(float2*)&Gb[li1 * 68 + c] = make_float2(gacc[j][2], gacc[j][3]);
        }
    }

    float oacc[4][4] = {};
    float m0r = -CUDART_INF_F, m1r = -CUDART_INF_F;
    float l0 = 0.0f, l1 = 0.0f;

    for (int t = 0; t < 32; t++) {
        __syncthreads();
        ld_split(kb + (size_t)t * 64 * QKVW, sm + SRSH, sm + SRSL, tid);
        ld_v(vb + (size_t)t * 64 * QKVW, sm + SVS, tid);
        __syncthreads();

        float cacc[4][4] = {};
        #pragma unroll
        for (int kk = 0; kk < 64; kk += 8) {
            int q0 = (kk >> 2) * 260, q1 = q0 + 260;
            int ma = 4 * li0 + tig, mb = ma + 32;
            uint32_t ah[4], al[4];
            ah[0] = FU(sm[SQCH + q0 + ma]); ah[1] = FU(sm[SQCH + q0 + mb]);
            ah[2] = FU(sm[SQCH + q1 + ma]); ah[3] = FU(sm[SQCH + q1 + mb]);
            al[0] = FU(sm[SQCL + q0 + ma]); al[1] = FU(sm[SQCL + q0 + mb]);
            al[2] = FU(sm[SQCL + q1 + ma]); al[3] = FU(sm[SQCL + q1 + mb]);
            #pragma unroll
            for (int j = 0; j < 4; j++) {
                int nb = 4 * (nwl + 8 * j + g) + tig;
                uint32_t bh2[2] = { FU(sm[SRSH + q0 + nb]), FU(sm[SRSH + q1 + nb]) };
                uint32_t bl2[2] = { FU(sm[SRSL + q0 + nb]), FU(sm[SRSL + q1 + nb]) };
                mma8x3(cacc[j], ah, al, bh2, bl2);
            }
        }
        __syncthreads();

        ld_split(g_relk + (size_t)(relbase + 64 * (t + 1)) * QKVW + h * 64,
                 sm + SRSH, sm + SRSL, tid);
        __syncthreads();

        {
            float gacc[4][4] = {};
            #pragma unroll
            for (int kk = 0; kk < 64; kk += 8) {
                int q0 = (kk >> 2) * 260, q1 = q0 + 260;
                int ma = 4 * li0 + tig, mb = ma + 32;
                uint32_t ah[4], al[4];
                ah[0] = FU(sm[SQPH + q0 + ma]); ah[1] = FU(sm[SQPH + q0 + mb]);
                ah[2] = FU(sm[SQPH + q1 + ma]); ah[3] = FU(sm[SQPH + q1 + mb]);
                al[0] = FU(sm[SQPL + q0 + ma]); al[1] = FU(sm[SQPL + q0 + mb]);
                al[2] = FU(sm[SQPL + q1 + ma]); al[3] = FU(sm[SQPL + q1 + mb]);
                #pragma unroll
                for (int j = 0; j < 4; j++) {
                    int nb = 4 * (nwl + 8 * j + g) + tig;
                    uint32_t bh2[2] = { FU(sm[SRSH + q0 + nb]), FU(sm[SRSH + q1 + nb]) };
                    uint32_t bl2[2] = { FU(sm[SRSL + q0 + nb]), FU(sm[SRSL + q1 + nb]) };
                    mma8x3(gacc[j], ah, al, bh2, bl2);
                }
            }
            float* Gb = sm + SGB + ((t + 1) & 1) * GSLOT;
            #pragma unroll
            for (int j = 0; j < 4; j++) {
                int c = nwl + 8 * j + 2 * tig;
                *(float2*)&Gb[li0 * 68 + c] = make_float2(gacc[j][0], gacc[j][1]);
                *(float2*)&Gb[li1 * 68 + c] = make_float2(gacc[j][2], gacc[j][3]);
            }
        }
        __syncthreads();

        const float* G0 = sm + SGB + (t & 1) * GSLOT;
        const float* G1 = sm + SGB + ((t + 1) & 1) * GSLOT;
        float s0[8], s1[8];
        float rm0 = -CUDART_INF_F, rm1 = -CUDART_INF_F;
        #pragma unroll
        for (int j = 0; j < 4; j++) {
            #pragma unroll
            for (int e = 0; e < 2; e++) {
                int lj = nwl + 8 * j + 2 * tig + e;
                int rl0 = lj - li0 + 63;
                int rl1 = lj - li1 + 63;
                float gv0 = (rl0 < 64) ? G0[li0 * 68 + rl0] : G1[li0 * 68 + rl0 - 64];
                float gv1 = (rl1 < 64) ? G0[li1 * 68 + rl1] : G1[li1 * 68 + rl1 - 64];
                float v0 = cacc[j][e]     + gv0;
                float v1 = cacc[j][2 + e] + gv1;
                s0[2 * j + e] = v0; s1[2 * j + e] = v1;
                rm0 = fmaxf(rm0, v0); rm1 = fmaxf(rm1, v1);
            }
        }
        rm0 = fmaxf(rm0, __shfl_xor_sync(0xFFFFFFFFu, rm0, 1));
        rm0 = fmaxf(rm0, __shfl_xor_sync(0xFFFFFFFFu, rm0, 2));
        rm1 = fmaxf(rm1, __shfl_xor_sync(0xFFFFFFFFu, rm1, 1));
        rm1 = fmaxf(rm1, __shfl_xor_sync(0xFFFFFFFFu, rm1, 2));
        if (tig == 0) {
            redm[(warp & 1) * 64 + li0] = rm0;
            redm[(warp & 1) * 64 + li1] = rm1;
        }
        __syncthreads();

        float mn0 = fmaxf(m0r, fmaxf(redm[li0], redm[64 + li0]));
        float mn1 = fmaxf(m1r, fmaxf(redm[li1], redm[64 + li1]));
        float sc0 = expf(m0r - mn0), sc1 = expf(m1r - mn1);
        m0r = mn0; m1r = mn1;
        float rs0 = 0.0f, rs1 = 0.0f;
        #pragma unroll
        for (int j = 0; j < 4; j++) {
            oacc[j][0] *= sc0; oacc[j][1] *= sc0;
            oacc[j][2] *= sc1; oacc[j][3] *= sc1;
            float p0a = expf(s0[2 * j] - mn0),     p0b = expf(s0[2 * j + 1] - mn0);
            float p1a = expf(s1[2 * j] - mn1),     p1b = expf(s1[2 * j + 1] - mn1);
            rs0 += p0a + p0b; rs1 += p1a + p1b;
            int c = nwl + 8 * j + 2 * tig;
            int base = (c >> 2) * 260 + (c & 3);
            float h0a = tfv(p0a), h0b = tfv(p0b), h1a = tfv(p1a), h1b = tfv(p1b);
            *(float2*)&sm[SPSH + base + 4 * li0] = make_float2(h0a, h0b);
            *(float2*)&sm[SPSH + base + 4 * li1] = make_float2(h1a, h1b);
            *(float2*)&sm[SPSL + base + 4 * li0] = make_float2(p0a - h0a, p0b - h0b);
            *(float2*)&sm[SPSL + base + 4 * li1] = make_float2(p1a - h1a, p1b - h1b);
        }
        rs0 += __shfl_xor_sync(0xFFFFFFFFu, rs0, 1);
        rs0 += __shfl_xor_sync(0xFFFFFFFFu, rs0, 2);
        rs1 += __shfl_xor_sync(0xFFFFFFFFu, rs1, 1);
        rs1 += __shfl_xor_sync(0xFFFFFFFFu, rs1, 2);
        if (tig == 0) {
            reds[(warp & 1) * 64 + li0] = rs0;
            reds[(warp & 1) * 64 + li1] = rs1;
        }
        __syncthreads();

        l0 = l0 * sc0 + reds[li0] + reds[64 + li0];
        l1 = l1 * sc1 + reds[li1] + reds[64 + li1];

        #pragma unroll
        for (int kk = 0; kk < 64; kk += 8) {
            int q0 = (kk >> 2) * 260, q1 = q0 + 260;
            int ma = 4 * li0 + tig, mb = ma + 32;
            uint32_t ph[4], pl[4];
            ph[0] = FU(sm[SPSH + q0 + ma]); ph[1] = FU(sm[SPSH + q0 + mb]);
            ph[2] = FU(sm[SPSH + q1 + ma]); ph[3] = FU(sm[SPSH + q1 + mb]);
            pl[0] = FU(sm[SPSL + q0 + ma]); pl[1] = FU(sm[SPSL + q0 + mb]);
            pl[2] = FU(sm[SPSL + q1 + ma]); pl[3] = FU(sm[SPSL + q1 + mb]);
            #pragma unroll
            for (int j = 0; j < 4; j++) {
                int nb = 4 * (nwl + 8 * j + g) + tig;
                uint32_t bf[2] = { FU(sm[SVS + q0 + nb]), FU(sm[SVS + q1 + nb]) };
                mma8(oacc[j], ph, bf);
                mma8(oacc[j], pl, bf);
            }
        }
    }

    float inv0 = 1.0f / l0, inv1 = 1.0f / l1;
    float* ob = g_o + (size_t)(b * NN + i0) * QKVW + h * 64;
    #pragma unroll
    for (int j = 0; j < 4; j++) {
        int c = nwl + 8 * j + 2 * tig;
        *(float2*)(ob + (size_t)li0 * QKVW + c) =
            make_float2(oacc[j][0] * inv0, oacc[j][1] * inv0);
        *(float2*)(ob + (size_t)li1 * QKVW + c) =
            make_float2(oacc[j][2] * inv1, oacc[j][3] * inv1);
    }
}

// ---------------- launch ----------------------------------------------------
static float* sym_addr(const void* sym) {
    void* p = nullptr;
    cudaGetSymbolAddress(&p, sym);
    return (float*)p;
}

extern "C" void kernel_launch(void* const* d_in, const int* in_sizes, int n_in,
                              void* d_out, int out_size) {
    const float* x    = (const float*)d_in[0];
    const float* Wq   = (const float*)d_in[1];
    const float* Wk   = (const float*)d_in[2];
    const float* Wv   = (const float*)d_in[3];
    const float* Wrel = (const float*)d_in[4];
    const float* Wout = (const float*)d_in[5];
    const float* bout = (const float*)d_in[6];
    const float* rcb  = (const float*)d_in[7];
    const float* rpb  = (const float*)d_in[8];
    float* out = (float*)d_out;

    float* p_pos  = sym_addr(g_pos);
    float* p_relk = sym_addr(g_relk);
    float* p_q    = sym_addr(g_q);
    float* p_k    = sym_addr(g_k);
    float* p_v    = sym_addr(g_v);
    float* p_o    = sym_addr(g_o);

    cudaFuncSetAttribute(gemm_tf32, cudaFuncAttributeMaxDynamicSharedMemorySize,
                         GEMM_SMEM);
    const int FUSED_SMEM = SM_TOT * 4;
    cudaFuncSetAttribute(attn_fused, cudaFuncAttributeMaxDynamicSharedMemorySize,
                         FUSED_SMEM);

    // 1. positional embedding
    pos_embed_kernel<<<LREL, 32>>>();

    // 2. rel_k = pos @ Wrel  (row 4095 of g_relk stays 0 = pad)
    gemm_tf32<<<dim3(QKVW / 64, 32, 1), 256, GEMM_SMEM>>>(
        p_pos, Wrel, nullptr, nullptr, nullptr, p_relk, nullptr, nullptr,
        LREL, FF, QKVW, FF, QKVW, QKVW);

    // 3. q,k,v projections fused into one launch (z selects weight/output)
    gemm_tf32<<<dim3(QKVW / 64, (BB * NN) / 128, 3), 256, GEMM_SMEM>>>(
        x, Wq, Wk, Wv, nullptr, p_q, p_k, p_v,
        BB * NN, DIMX, QKVW, DIMX, QKVW, QKVW);

    // 4. fused logits + online softmax + P@V
    attn_fused<<<dim3(NN / 64, BB * HH), 256, FUSED_SMEM>>>(rcb, rpb);

    // 5. out = O @ Wout + b_out
    gemm_tf32<<<dim3(DIMX / 64, (BB * NN) / 128, 1), 256, GEMM_SMEM>>>(
        p_o, Wout, nullptr, nullptr, bout, out, nullptr, nullptr,
        BB * NN, QKVW, DIMX, QKVW, DIMX, DIMX);
}

// round 12
// speedup vs baseline: 1.5796x; 1.0315x over previous
#include <cuda_runtime.h>
#include <math.h>
#include <math_constants.h>
#include <stdint.h>

// Problem constants
#define BB 2
#define NN 2048
#define DIMX 768
#define HH 8
#define FF 192
#define LREL 4095            // 2*N - 1
#define QKVW 512             // H * DK

// ---------------- scratch (device globals; no allocation allowed) ----------
__device__ __align__(256) float g_pos[(size_t)LREL * FF];
__device__ __align__(256) float g_relk[(size_t)(LREL + 1) * QKVW]; // +1 pad row (stays 0)
__device__ __align__(256) float g_q[(size_t)BB * NN * QKVW];       // [b][n][h*64+d]
__device__ __align__(256) float g_k[(size_t)BB * NN * QKVW];
__device__ __align__(256) float g_v[(size_t)BB * NN * QKVW];
__device__ __align__(256) float g_o[(size_t)BB * NN * QKVW];

// ---------------- tf32 mma helpers -----------------------------------------
__device__ __forceinline__ uint32_t f2tf(float x) {
    uint32_t r; asm("cvt.rna.tf32.f32 %0, %1;" : "=r"(r) : "f"(x));
    return r;
}
__device__ __forceinline__ float tfv(float x) { return __uint_as_float(f2tf(x)); }
__device__ __forceinline__ void mma8(float* d, const uint32_t* a, const uint32_t* b) {
    asm volatile(
        "mma.sync.aligned.m16n8k8.row.col.f32.tf32.tf32.f32 "
        "{%0,%1,%2,%3},{%4,%5,%6,%7},{%8,%9},{%0,%1,%2,%3};\n"
        : "+f"(d[0]), "+f"(d[1]), "+f"(d[2]), "+f"(d[3])
        : "r"(a[0]), "r"(a[1]), "r"(a[2]), "r"(a[3]), "r"(b[0]), "r"(b[1]));
}
__device__ __forceinline__ void mma8x3(float* d, const uint32_t* ahi, const uint32_t* alo,
                                       const uint32_t* bhi, const uint32_t* blo) {
    mma8(d, ahi, blo);
    mma8(d, alo, bhi);
    mma8(d, ahi, bhi);
}
#define FU(x) __float_as_uint(x)

// ---------------- K1: positional embedding ----------------------------------
__global__ void pos_embed_kernel() {
    int row = blockIdx.x;
    int i = threadIdx.x;
    float dist = (float)(row - (NN - 1));
    float ad = fabsf(dist);

    float half_life = exp2f(3.0f + 8.0f * (float)i / 31.0f);
    float f_exp = exp2f(-ad / half_life);

    float width = exp2f((float)(i + 1)) - 1.0f;
    float f_cm = (width > ad) ? 1.0f : 0.0f;

    float mean = 64.0f * (float)(i + 1);
    float conc = (mean / 32.0f) * (mean / 32.0f);
    float rate = mean / 1024.0f;
    float log_unnorm = (conc - 1.0f) * logf(ad) - rate * ad;
    float log_norm = lgammaf(conc) - conc * logf(rate);
    float prob = expf(log_unnorm - log_norm) + 1e-8f;
    float pmax = prob;
    #pragma unroll
    for (int o = 16; o; o >>= 1) pmax = fmaxf(pmax, __shfl_xor_sync(0xFFFFFFFFu, pmax, o));
    float f_g = prob / pmax;

    float sgn = (dist > 0.0f) ? 1.0f : ((dist < 0.0f) ? -1.0f : 0.0f);

    float* out = g_pos + (size_t)row * FF;
    out[i]       = f_exp;
    out[32 + i]  = f_cm;
    out[64 + i]  = f_g;
    out[96 + i]  = sgn * f_exp;
    out[128 + i] = sgn * f_cm;
    out[160 + i] = sgn * f_g;
}

// ---------------- K2: tf32x3 GEMM v2 (unchanged from round 9) ---------------
#define GA 516
#define GB 260
#define VAH 0
#define VAL 4128
#define VBH 8256
#define VBL 10336
#define GEMM_SMEM ((10336 + 2080) * 4)
__global__ __launch_bounds__(256) void gemm_tf32(
    const float* __restrict__ A, const float* __restrict__ B0,
    const float* __restrict__ B1, const float* __restrict__ B2,
    const float* __restrict__ bias, float* __restrict__ C0,
    float* __restrict__ C1, float* __restrict__ C2,
    int M, int K, int Nc, int lda, int ldb, int ldc) {
    extern __shared__ float sg[];
    float* sAh = sg + VAH; float* sAl = sg + VAL;
    float* sBh = sg + VBH; float* sBl = sg + VBL;

    const float* B = B0;
    float* C = C0;
    if (blockIdx.z == 1) { B = B1; C = C1; }
    else if (blockIdx.z == 2) { B = B2; C = C2; }

    int tid = threadIdx.x;
    int warp = tid >> 5, lane = tid & 31;
    int g = lane >> 2, tig = lane & 3;
    int mw = (warp >> 1) * 32, nw = (warp & 1) * 32;
    int m0 = blockIdx.y * 128, n0 = blockIdx.x * 64;

    float acc[2][4][4] = {};

    int am = tid & 127, akg0 = tid >> 7;
    int bn = tid & 63,  bkg0 = tid >> 6;

    for (int k0 = 0; k0 < K; k0 += 32) {
        #pragma unroll
        for (int r = 0; r < 4; r++) {
            int kg = akg0 + 2 * r;
            int m = m0 + am;
            float4 v = make_float4(0.f, 0.f, 0.f, 0.f);
            if (m < M) v = *(const float4*)(A + (size_t)m * lda + k0 + kg * 4);
            float h0 = tfv(v.x), h1 = tfv(v.y), h2 = tfv(v.z), h3 = tfv(v.w);
            *(float4*)&sAh[kg * GA + am * 4] = make_float4(h0, h1, h2, h3);
            *(float4*)&sAl[kg * GA + am * 4] =
                make_float4(v.x - h0, v.y - h1, v.z - h2, v.w - h3);
        }
        #pragma unroll
        for (int r = 0; r < 2; r++) {
            int kg = bkg0 + 4 * r;
            const float* bp = B + (size_t)(k0 + kg * 4) * ldb + n0 + bn;
            float x0 = bp[0];
            float x1 = bp[(size_t)ldb];
            float x2 = bp[2 * (size_t)ldb];
            float x3 = bp[3 * (size_t)ldb];
            float h0 = tfv(x0), h1 = tfv(x1), h2 = tfv(x2), h3 = tfv(x3);
            *(float4*)&sBh[kg * GB + bn * 4] = make_float4(h0, h1, h2, h3);
            *(float4*)&sBl[kg * GB + bn * 4] =
                make_float4(x0 - h0, x1 - h1, x2 - h2, x3 - h3);
        }
        __syncthreads();
        #pragma unroll
        for (int kk = 0; kk < 32; kk += 8) {
            int qa = (kk >> 2) * GA, qb2 = (kk >> 2) * GB;
            uint32_t ah[2][4], al[2][4], bhf[4][2], blf[4][2];
            #pragma unroll
            for (int f = 0; f < 2; f++) {
                int ma = (mw + 16 * f + g) * 4 + tig;
                ah[f][0] = FU(sAh[qa + ma]);
                ah[f][1] = FU(sAh[qa + ma + 32]);
                ah[f][2] = FU(sAh[qa + GA + ma]);
                ah[f][3] = FU(sAh[qa + GA + ma + 32]);
                al[f][0] = FU(sAl[qa + ma]);
                al[f][1] = FU(sAl[qa + ma + 32]);
                al[f][2] = FU(sAl[qa + GA + ma]);
                al[f][3] = FU(sAl[qa + GA + ma + 32]);
            }
            #pragma unroll
            for (int j = 0; j < 4; j++) {
                int nb = (nw + 8 * j + g) * 4 + tig;
                bhf[j][0] = FU(sBh[qb2 + nb]);
                bhf[j][1] = FU(sBh[qb2 + GB + nb]);
                blf[j][0] = FU(sBl[qb2 + nb]);
                blf[j][1] = FU(sBl[qb2 + GB + nb]);
            }
            #pragma unroll
            for (int f = 0; f < 2; f++)
                #pragma unroll
                for (int j = 0; j < 4; j++) mma8(acc[f][j], ah[f], bhf[j]);
            #pragma unroll
            for (int f = 0; f < 2; f++)
                #pragma unroll
                for (int j = 0; j < 4; j++) mma8(acc[f][j], ah[f], blf[j]);
            #pragma unroll
            for (int f = 0; f < 2; f++)
                #pragma unroll
                for (int j = 0; j < 4; j++) mma8(acc[f][j], al[f], bhf[j]);
        }
        __syncthreads();
    }

    #pragma unroll
    for (int f = 0; f < 2; f++) {
        #pragma unroll
        for (int j = 0; j < 4; j++) {
            int n = n0 + nw + 8 * j + 2 * tig;
            float b0v = bias ? bias[n] : 0.0f;
            float b1v = bias ? bias[n + 1] : 0.0f;
            int m = m0 + mw + 16 * f + g;
            if (m < M)
                *(float2*)(C + (size_t)m * ldc + n) =
                    make_float2(acc[f][j][0] + b0v, acc[f][j][1] + b1v);
            if (m + 8 < M)
                *(float2*)(C + (size_t)(m + 8) * ldc + n) =
                    make_float2(acc[f][j][2] + b0v, acc[f][j][3] + b1v);
        }
    }
}

// ---------------- K3: fused attention v2 ------------------------------------
// Q regs + bias-vector trick + interleaved hi/lo smem + 5 syncs/iter.
// Interleaved layout: elem (k,n) -> (k>>2)*GI + POS8(n) + 2*(k&3) (+1 for lo)
#define GI 546
#define POS8(n) (8 * (n) + 2 * ((n) >> 2))
#define FRK 0                      // K tile   16*546 = 8736
#define FRB 8736                   // band tile 8736
#define FPS 17472                  // P tile (also Qraw temp) 8736
#define FVS 26208                  // V tile 16*260 = 4160
#define FGB 30368                  // G buf 2 * 4352
#define FCB 39072                  // cb[64]
#define FDB 39136                  // db[2][64]
#define FREDM 39264                // 128
#define FREDS 39392                // 128
#define FSM_TOT 39520              // *4 = 158,080 B
#define GSLOT2 4352

// split-load 64x64 tile (row-major, ld=QKVW) into interleaved hi/lo k4 layout
__device__ __forceinline__ void ld_split_i(const float* src, float* dst, int tid) {
    int n = tid & 63, dg = tid >> 6;
    #pragma unroll
    for (int r = 0; r < 4; r++) {
        int grp = dg + 4 * r;
        float4 v = *(const float4*)(src + (size_t)n * QKVW + grp * 4);
        float h0 = tfv(v.x), h1 = tfv(v.y), h2 = tfv(v.z), h3 = tfv(v.w);
        int base = grp * GI + POS8(n);
        *(float2*)&dst[base + 0] = make_float2(h0, v.x - h0);
        *(float2*)&dst[base + 2] = make_float2(h1, v.y - h1);
        *(float2*)&dst[base + 4] = make_float2(h2, v.z - h2);
        *(float2*)&dst[base + 6] = make_float2(h3, v.w - h3);
    }
}
// V loader: plain k4 B-operand layout (k = seq row, n = dv), rna-rounded
__device__ __forceinline__ void ld_v(const float* src, float* dv, int tid) {
    int row = tid & 63, dg = tid >> 6;
    #pragma unroll
    for (int r = 0; r < 4; r++) {
        int grp = dg + 4 * r;
        float4 v = *(const float4*)(src + (size_t)row * QKVW + grp * 4);
        int bb = (row >> 2) * 260 + (row & 3);
        dv[bb + (grp * 4 + 0) * 4] = tfv(v.x);
        dv[bb + (grp * 4 + 1) * 4] = tfv(v.y);
        dv[bb + (grp * 4 + 2) * 4] = tfv(v.z);
        dv[bb + (grp * 4 + 3) * 4] = tfv(v.w);
    }
}

__global__ __launch_bounds__(256, 1) void attn_fused(const float* __restrict__ rcb,
                                                     const float* __restrict__ rpb) {
    extern __shared__ float sm[];

    int bhid = blockIdx.y;
    int b = bhid >> 3, h = bhid & 7;
    int i0 = blockIdx.x * 64;
    int tid = threadIdx.x, warp = tid >> 5, lane = tid & 31;
    int g = lane >> 2, tig = lane & 3;
    int mwl = (warp >> 1) * 16, nwl = (warp & 1) * 32;
    int li0 = mwl + g, li1 = li0 + 8;

    const float* qb = g_q + (size_t)b * NN * QKVW + h * 64;
    const float* kb = g_k + (size_t)b * NN * QKVW + h * 64;
    const float* vb = g_v + (size_t)b * NN * QKVW + h * 64;
    int relbase = 1984 - i0;

    // ---- prologue: Qraw (scaled) -> FPS temp; band chunk0 -> FRB ----
    {
        int row = tid & 63, dg = tid >> 6;
        #pragma unroll
        for (int r = 0; r < 4; r++) {
            int grp = dg + 4 * r;
            float4 v = *(const float4*)(qb + (size_t)(i0 + row) * QKVW + grp * 4);
            *(float4*)&sm[FPS + row * 68 + grp * 4] =
                make_float4(v.x * 0.125f, v.y * 0.125f, v.z * 0.125f, v.w * 0.125f);
        }
    }
    ld_split_i(g_relk + (size_t)relbase * QKVW + h * 64, sm + FRB, tid);
    __syncthreads();

    // extract Q fragments to registers (hi/lo)
    uint32_t qh[8][4], ql[8][4];
    #pragma unroll
    for (int kkg = 0; kkg < 8; kkg++) {
        int kk = 8 * kkg;
        float a0 = sm[FPS + li0 * 68 + kk + tig];
        float a1 = sm[FPS + li1 * 68 + kk + tig];
        float a2 = sm[FPS + li0 * 68 + kk + tig + 4];
        float a3 = sm[FPS + li1 * 68 + kk + tig + 4];
        float h0 = tfv(a0), h1 = tfv(a1), h2 = tfv(a2), h3 = tfv(a3);
        qh[kkg][0] = FU(h0); qh[kkg][1] = FU(h1); qh[kkg][2] = FU(h2); qh[kkg][3] = FU(h3);
        ql[kkg][0] = FU(tfv(a0 - h0)); ql[kkg][1] = FU(tfv(a1 - h1));
        ql[kkg][2] = FU(tfv(a2 - h2)); ql[kkg][3] = FU(tfv(a3 - h3));
    }

    // db[0] from band chunk0 (d = (tid&3) + 4*dd striding: conflict-free)
    {
        int col = tid >> 2;
        float accd = 0.0f;
        #pragma unroll
        for (int dd = 0; dd < 16; dd++) {
            int d = (tid & 3) + 4 * dd;
            float2 bv = *(float2*)&sm[FRB + dd * GI + POS8(col) + 2 * (tid & 3)];
            accd = fmaf(rpb[h * 64 + d], bv.x + bv.y, accd);
        }
        accd += __shfl_xor_sync(0xFFFFFFFFu, accd, 1);
        accd += __shfl_xor_sync(0xFFFFFFFFu, accd, 2);
        if ((tid & 3) == 0) sm[FDB + col] = accd;
    }

    // G chunk0 -> Gbuf slot 0
    {
        float gacc[4][4] = {};
        #pragma unroll
        for (int kkg = 0; kkg < 8; kkg++) {
            int g0 = (2 * kkg) * GI, g1 = g0 + GI;
            #pragma unroll
            for (int j = 0; j < 4; j++) {
                int nb = POS8(nwl + 8 * j + g) + 2 * tig;
                float2 b0 = *(float2*)&sm[FRB + g0 + nb];
                float2 b1 = *(float2*)&sm[FRB + g1 + nb];
                uint32_t bh2[2] = { FU(b0.x), FU(b1.x) };
                uint32_t bl2[2] = { FU(b0.y), FU(b1.y) };
                mma8x3(gacc[j], qh[kkg], ql[kkg], bh2, bl2);
            }
        }
        float* Gb = sm + FGB;
        #pragma unroll
        for (int j = 0; j < 4; j++) {
            int c = nwl + 8 * j + 2 * tig;
            *(float2*)&Gb[li0 * 68 + c] = make_float2(gacc[j][0], gacc[j][1]);
            *(float2*)&Gb[li1 * 68 + c] = make_float2(gacc[j][2], gacc[j][3]);
        }
    }

    float oacc[4][4] = {};
    float m0r = -CUDART_INF_F, m1r = -CUDART_INF_F;
    float l0 = 0.0f, l1 = 0.0f;

    for (int t = 0; t < 32; t++) {
        __syncthreads();   // S1: prior consumers done
        ld_split_i(kb + (size_t)t * 64 * QKVW, sm + FRK, tid);
        ld_v(vb + (size_t)t * 64 * QKVW, sm + FVS, tid);
        ld_split_i(g_relk + (size_t)(relbase + 64 * (t + 1)) * QKVW + h * 64,
                   sm + FRB, tid);
        __syncthreads();   // S2: loads visible

        // cb (from K) and db[(t+1)&1] (from band)
        {
            int col = tid >> 2;
            float accc = 0.0f, accd = 0.0f;
            #pragma unroll
            for (int dd = 0; dd < 16; dd++) {
                int d = (tid & 3) + 4 * dd;
                int off = dd * GI + POS8(col) + 2 * (tid & 3);
                float2 kv = *(float2*)&sm[FRK + off];
                float2 bv = *(float2*)&sm[FRB + off];
                float w1 = rcb[h * 64 + d], w2 = rpb[h * 64 + d];
                accc = fmaf(w1, kv.x + kv.y, accc);
                accd = fmaf(w2, bv.x + bv.y, accd);
            }
            accc += __shfl_xor_sync(0xFFFFFFFFu, accc, 1);
            accc += __shfl_xor_sync(0xFFFFFFFFu, accc, 2);
            accd += __shfl_xor_sync(0xFFFFFFFFu, accd, 1);
            accd += __shfl_xor_sync(0xFFFFFFFFu, accd, 2);
            if ((tid & 3) == 0) {
                sm[FCB + col] = accc;
                sm[FDB + ((t + 1) & 1) * 64 + col] = accd;
            }
        }

        // content mma: cacc = Q x K
        float cacc[4][4] = {};
        #pragma unroll
        for (int kkg = 0; kkg < 8; kkg++) {
            int g0 = (2 * kkg) * GI, g1 = g0 + GI;
            #pragma unroll
            for (int j = 0; j < 4; j++) {
                int nb = POS8(nwl + 8 * j + g) + 2 * tig;
                float2 b0 = *(float2*)&sm[FRK + g0 + nb];
                float2 b1 = *(float2*)&sm[FRK + g1 + nb];
                uint32_t bh2[2] = { FU(b0.x), FU(b1.x) };
                uint32_t bl2[2] = { FU(b0.y), FU(b1.y) };
                mma8x3(cacc[j], qh[kkg], ql[kkg], bh2, bl2);
            }
        }

        // G mma chunk t+1 -> Gbuf slot (t+1)&1
        {
            float gacc[4][4] = {};
            #pragma unroll
            for (int kkg = 0; kkg < 8; kkg++) {
                int g0 = (2 * kkg) * GI, g1 = g0 + GI;
                #pragma unroll
                for (int j = 0; j < 4; j++) {
                    int nb = POS8(nwl + 8 * j + g) + 2 * tig;
                    float2 b0 = *(float2*)&sm[FRB + g0 + nb];
                    float2 b1 = *(float2*)&sm[FRB + g1 + nb];
                    uint32_t bh2[2] = { FU(b0.x), FU(b1.x) };
                    uint32_t bl2[2] = { FU(b0.y), FU(b1.y) };
                    mma8x3(gacc[j], qh[kkg], ql[kkg], bh2, bl2);
                }
            }
            float* Gb = sm + FGB + ((t + 1) & 1) * GSLOT2;
            #pragma unroll
            for (int j = 0; j < 4; j++) {
                int c = nwl + 8 * j + 2 * tig;
                *(float2*)&Gb[li0 * 68 + c] = make_float2(gacc[j][0], gacc[j][1]);
                *(float2*)&Gb[li1 * 68 + c] = make_float2(gacc[j][2], gacc[j][3]);
            }
        }
        __syncthreads();   // S3: Gbuf + cb + db visible

        // gather + biases + rowmax
        const float* G0 = sm + FGB + (t & 1) * GSLOT2;
        const float* G1 = sm + FGB + ((t + 1) & 1) * GSLOT2;
        const float* db0 = sm + FDB + (t & 1) * 64;
        const float* db1 = sm + FDB + ((t + 1) & 1) * 64;
        float s0[8], s1[8];
        float rm0 = -CUDART_INF_F, rm1 = -CUDART_INF_F;
        #pragma unroll
        for (int j = 0; j < 4; j++) {
            #pragma unroll
            for (int e = 0; e < 2; e++) {
                int lj = nwl + 8 * j + 2 * tig + e;
                float cbv = sm[FCB + lj];
                int rl0 = lj - li0 + 63;
                int rl1 = lj - li1 + 63;
                float gv0 = (rl0 < 64) ? (G0[li0 * 68 + rl0] + db0[rl0])
                                       : (G1[li0 * 68 + rl0 - 64] + db1[rl0 - 64]);
                float gv1 = (rl1 < 64) ? (G0[li1 * 68 + rl1] + db0[rl1])
                                       : (G1[li1 * 68 + rl1 - 64] + db1[rl1 - 64]);
                float v0 = cacc[j][e]     + gv0 + cbv;
                float v1 = cacc[j][2 + e] + gv1 + cbv;
                s0[2 * j + e] = v0; s1[2 * j + e] = v1;
                rm0 = fmaxf(rm0, v0); rm1 = fmaxf(rm1, v1);
            }
        }
        rm0 = fmaxf(rm0, __shfl_xor_sync(0xFFFFFFFFu, rm0, 1));
        rm0 = fmaxf(rm0, __shfl_xor_sync(0xFFFFFFFFu, rm0, 2));
        rm1 = fmaxf(rm1, __shfl_xor_sync(0xFFFFFFFFu, rm1, 1));
        rm1 = fmaxf(rm1, __shfl_xor_sync(0xFFFFFFFFu, rm1, 2));
        if (tig == 0) {
            sm[FREDM + (warp & 1) * 64 + li0] = rm0;
            sm[FREDM + (warp & 1) * 64 + li1] = rm1;
        }
        __syncthreads();   // S4: redm visible

        float mn0 = fmaxf(m0r, fmaxf(sm[FREDM + li0], sm[FREDM + 64 + li0]));
        float mn1 = fmaxf(m1r, fmaxf(sm[FREDM + li1], sm[FREDM + 64 + li1]));
        float sc0 = __expf(m0r - mn0), sc1 = __expf(m1r - mn1);
        m0r = mn0; m1r = mn1;
        float rs0 = 0.0f, rs1 = 0.0f;
        #pragma unroll
        for (int j = 0; j < 4; j++) {
            oacc[j][0] *= sc0; oacc[j][1] *= sc0;
            oacc[j][2] *= sc1; oacc[j][3] *= sc1;
            float p0a = __expf(s0[2 * j] - mn0), p0b = __expf(s0[2 * j + 1] - mn0);
            float p1a = __expf(s1[2 * j] - mn1), p1b = __expf(s1[2 * j + 1] - mn1);
            rs0 += p0a + p0b; rs1 += p1a + p1b;
            int c = nwl + 8 * j + 2 * tig;
            int pb = FPS + (c >> 2) * GI + 2 * (c & 3);
            float h0a = tfv(p0a), h0b = tfv(p0b), h1a = tfv(p1a), h1b = tfv(p1b);
            *(float2*)&sm[pb + POS8(li0)]     = make_float2(h0a, p0a - h0a);
            *(float2*)&sm[pb + POS8(li0) + 2] = make_float2(h0b, p0b - h0b);
            *(float2*)&sm[pb + POS8(li1)]     = make_float2(h1a, p1a - h1a);
            *(float2*)&sm[pb + POS8(li1) + 2] = make_float2(h1b, p1b - h1b);
        }
        rs0 += __shfl_xor_sync(0xFFFFFFFFu, rs0, 1);
        rs0 += __shfl_xor_sync(0xFFFFFFFFu, rs0, 2);
        rs1 += __shfl_xor_sync(0xFFFFFFFFu, rs1, 1);
        rs1 += __shfl_xor_sync(0xFFFFFFFFu, rs1, 2);
        if (tig == 0) {
            sm[FREDS + (warp & 1) * 64 + li0] = rs0;
            sm[FREDS + (warp & 1) * 64 + li1] = rs1;
        }
        __syncthreads();   // S5: P + reds visible

        l0 = l0 * sc0 + sm[FREDS + li0] + sm[FREDS + 64 + li0];
        l1 = l1 * sc1 + sm[FREDS + li1] + sm[FREDS + 64 + li1];

        // PV mma: oacc += P x V  (P split x2, V rna)
        #pragma unroll
        for (int kkg = 0; kkg < 8; kkg++) {
            int pg0 = FPS + (2 * kkg) * GI, pg1 = pg0 + GI;
            float2 p0 = *(float2*)&sm[pg0 + POS8(li0) + 2 * tig];
            float2 p1 = *(float2*)&sm[pg0 + POS8(li1) + 2 * tig];
            float2 p2 = *(float2*)&sm[pg1 + POS8(li0) + 2 * tig];
            float2 p3 = *(float2*)&sm[pg1 + POS8(li1) + 2 * tig];
            uint32_t ph[4] = { FU(p0.x), FU(p1.x), FU(p2.x), FU(p3.x) };
            uint32_t pl[4] = { FU(p0.y), FU(p1.y), FU(p2.y), FU(p3.y) };
            #pragma unroll
            for (int j = 0; j < 4; j++) {
                int n = nwl + 8 * j + g;
                uint32_t bf[2] = { FU(sm[FVS + 2 * kkg * 260 + 4 * n + tig]),
                                   FU(sm[FVS + (2 * kkg + 1) * 260 + 4 * n + tig]) };
                mma8(oacc[j], ph, bf);
                mma8(oacc[j], pl, bf);
            }
        }
    }

    float inv0 = 1.0f / l0, inv1 = 1.0f / l1;
    float* ob = g_o + (size_t)(b * NN + i0) * QKVW + h * 64;
    #pragma unroll
    for (int j = 0; j < 4; j++) {
        int c = nwl + 8 * j + 2 * tig;
        *(float2*)(ob + (size_t)li0 * QKVW + c) =
            make_float2(oacc[j][0] * inv0, oacc[j][1] * inv0);
        *(float2*)(ob + (size_t)li1 * QKVW + c) =
            make_float2(oacc[j][2] * inv1, oacc[j][3] * inv1);
    }
}

// ---------------- launch ----------------------------------------------------
static float* sym_addr(const void* sym) {
    void* p = nullptr;
    cudaGetSymbolAddress(&p, sym);
    return (float*)p;
}

extern "C" void kernel_launch(void* const* d_in, const int* in_sizes, int n_in,
                              void* d_out, int out_size) {
    const float* x    = (const float*)d_in[0];
    const float* Wq   = (const float*)d_in[1];
    const float* Wk   = (const float*)d_in[2];
    const float* Wv   = (const float*)d_in[3];
    const float* Wrel = (const float*)d_in[4];
    const float* Wout = (const float*)d_in[5];
    const float* bout = (const float*)d_in[6];
    const float* rcb  = (const float*)d_in[7];
    const float* rpb  = (const float*)d_in[8];
    float* out = (float*)d_out;

    float* p_pos  = sym_addr(g_pos);
    float* p_relk = sym_addr(g_relk);
    float* p_q    = sym_addr(g_q);
    float* p_k    = sym_addr(g_k);
    float* p_v    = sym_addr(g_v);
    float* p_o    = sym_addr(g_o);

    cudaFuncSetAttribute(gemm_tf32, cudaFuncAttributeMaxDynamicSharedMemorySize,
                         GEMM_SMEM);
    const int FUSED_SMEM = FSM_TOT * 4;   // 158,080 B
    cudaFuncSetAttribute(attn_fused, cudaFuncAttributeMaxDynamicSharedMemorySize,
                         FUSED_SMEM);

    // 1. positional embedding
    pos_embed_kernel<<<LREL, 32>>>();

    // 2. rel_k = pos @ Wrel  (row 4095 of g_relk stays 0 = pad)
    gemm_tf32<<<dim3(QKVW / 64, 32, 1), 256, GEMM_SMEM>>>(
        p_pos, Wrel, nullptr, nullptr, nullptr, p_relk, nullptr, nullptr,
        LREL, FF, QKVW, FF, QKVW, QKVW);

    // 3. q,k,v projections fused into one launch
    gemm_tf32<<<dim3(QKVW / 64, (BB * NN) / 128, 3), 256, GEMM_SMEM>>>(
        x, Wq, Wk, Wv, nullptr, p_q, p_k, p_v,
        BB * NN, DIMX, QKVW, DIMX, QKVW, QKVW);

    // 4. fused logits + online softmax + P@V
    attn_fused<<<dim3(NN / 64, BB * HH), 256, FUSED_SMEM>>>(rcb, rpb);

    // 5. out = O @ Wout + b_out
    gemm_tf32<<<dim3(DIMX / 64, (BB * NN) / 128, 1), 256, GEMM_SMEM>>>(
        p_o, Wout, nullptr, nullptr, bout, out, nullptr, nullptr,
        BB * NN, QKVW, DIMX, QKVW, DIMX, DIMX);
}